// round 1
// baseline (speedup 1.0000x reference)
#include <cuda_runtime.h>
#include <math.h>

#define Bz 256
#define Sz 128
#define Hz 14
#define Wz 14
#define Tz 12
#define Dz 512
#define HWz (Hz*Wz)
#define Mbig (Bz*HWz)   // 50176

// ---------------- scratch (device globals; no allocation) ----------------
__device__ float g_qi[Bz*Dz];
__device__ float g_cqi[Bz*Dz];
__device__ float g_cai[Bz*Sz];
__device__ float g_ci[Bz*Dz];
__device__ float g_rm[Bz*Dz];
__device__ float g_rk[(size_t)Mbig*Dz];
__device__ float g_ip[(size_t)Mbig*Dz];
__device__ float g_rai[(size_t)Mbig*Dz];
__device__ float g_ri[Bz*Dz];
__device__ float g_mi_info[Bz*Dz];
__device__ float g_mi_sa[Bz*Dz];
__device__ float g_mi_prime[Bz*Dz];

// ---------------- generic fp32 SGEMM: C[M,N] (+)= (scale ⊙ A)[M,K] @ Bw[K,N] + bias ----------------
// scale (optional): per-batch row scaling, batch = row / rpb, scale shape [B,K].
__global__ void __launch_bounds__(256) sgemm_kernel(
    const float* __restrict__ A, const float* __restrict__ Bw,
    const float* __restrict__ bias, float* __restrict__ C,
    int M, int N, int K,
    const float* __restrict__ scale, int rpb, int acc_flag)
{
    __shared__ float As[8][128];
    __shared__ float Bs[8][128];
    const int tid = threadIdx.x;
    const int m0 = blockIdx.y * 128;
    const int n0 = blockIdx.x * 128;
    const int tx = tid & 15;
    const int ty = tid >> 4;

    const int aRow = tid >> 1;
    const int aCol = (tid & 1) << 2;
    const int bRow = tid >> 5;
    const int bCol = (tid & 31) << 2;

    float acc[8][8];
    #pragma unroll
    for (int i = 0; i < 8; i++)
        #pragma unroll
        for (int j = 0; j < 8; j++) acc[i][j] = 0.f;

    const float* Aptr = A + (size_t)(m0 + aRow) * K + aCol;
    const float* Sptr = nullptr;
    if (scale) Sptr = scale + (size_t)((m0 + aRow) / rpb) * K + aCol;

    for (int kt = 0; kt < K; kt += 8) {
        float4 a = *(const float4*)(Aptr + kt);
        if (Sptr) {
            float4 s = *(const float4*)(Sptr + kt);
            a.x *= s.x; a.y *= s.y; a.z *= s.z; a.w *= s.w;
        }
        As[aCol + 0][aRow] = a.x;
        As[aCol + 1][aRow] = a.y;
        As[aCol + 2][aRow] = a.z;
        As[aCol + 3][aRow] = a.w;

        float4 b = *(const float4*)(Bw + (size_t)(kt + bRow) * N + n0 + bCol);
        *(float4*)&Bs[bRow][bCol] = b;
        __syncthreads();

        #pragma unroll
        for (int k = 0; k < 8; k++) {
            float ar[8], br[8];
            #pragma unroll
            for (int i = 0; i < 8; i++) ar[i] = As[k][ty * 8 + i];
            #pragma unroll
            for (int j = 0; j < 8; j++) br[j] = Bs[k][tx * 8 + j];
            #pragma unroll
            for (int i = 0; i < 8; i++)
                #pragma unroll
                for (int j = 0; j < 8; j++)
                    acc[i][j] = fmaf(ar[i], br[j], acc[i][j]);
        }
        __syncthreads();
    }

    #pragma unroll
    for (int i = 0; i < 8; i++) {
        int row = m0 + ty * 8 + i;
        float* crow = C + (size_t)row * N + n0 + tx * 8;
        #pragma unroll
        for (int j = 0; j < 8; j++) {
            float v = acc[i][j];
            if (bias) v += bias[n0 + tx * 8 + j];
            if (acc_flag) v += crow[j];
            crow[j] = v;
        }
    }
}

// ---------------- cai[b,s] = sum_d cqi[b,d]*cws[b,s,d]*W_cai[d]  (bias cancels in softmax) ----------------
__global__ void __launch_bounds__(256) cai_kernel(const float* __restrict__ cws,
                                                  const float* __restrict__ Wcai)
{
    int warp = (blockIdx.x * blockDim.x + threadIdx.x) >> 5;
    int lane = threadIdx.x & 31;
    if (warp >= Bz * Sz) return;
    int b = warp / Sz;
    const float* cq = g_cqi + b * Dz;
    const float* cw = cws + (size_t)warp * Dz;
    float sum = 0.f;
    #pragma unroll 4
    for (int d = lane; d < Dz; d += 32)
        sum += cq[d] * cw[d] * Wcai[d];
    #pragma unroll
    for (int o = 16; o; o >>= 1) sum += __shfl_xor_sync(0xffffffffu, sum, o);
    if (lane == 0) g_cai[warp] = sum;
}

// ---------------- softmax over S, then ci[b,d] = sum_s w[s]*cws[b,s,d] ----------------
__global__ void __launch_bounds__(128) ci_kernel(const float* __restrict__ cws)
{
    int b = blockIdx.x, tid = threadIdx.x;  // 128 threads
    __shared__ float wsm[Sz];
    __shared__ float red[4];
    float x = g_cai[b * Sz + tid];
    float m = x;
    #pragma unroll
    for (int o = 16; o; o >>= 1) m = fmaxf(m, __shfl_xor_sync(0xffffffffu, m, o));
    if ((tid & 31) == 0) red[tid >> 5] = m;
    __syncthreads();
    float bm = fmaxf(fmaxf(red[0], red[1]), fmaxf(red[2], red[3]));
    __syncthreads();
    float e = expf(x - bm);
    float s = e;
    #pragma unroll
    for (int o = 16; o; o >>= 1) s += __shfl_xor_sync(0xffffffffu, s, o);
    if ((tid & 31) == 0) red[tid >> 5] = s;
    __syncthreads();
    float bs = red[0] + red[1] + red[2] + red[3];
    wsm[tid] = e / bs;
    __syncthreads();
    for (int d = tid; d < Dz; d += 128) {
        float acc = 0.f;
        #pragma unroll 8
        for (int s2 = 0; s2 < Sz; s2++)
            acc += wsm[s2] * cws[((size_t)b * Sz + s2) * Dz + d];
        g_ci[b * Dz + d] = acc;
    }
}

// ---------------- double softmax (over H, then over W of probs) + ri = sum rvi*K ----------------
__global__ void __launch_bounds__(512) rsoft_kernel(const float* __restrict__ Kt)
{
    int b = blockIdx.x;
    int d = threadIdx.x;  // 512
    float* r = g_rai + (size_t)b * HWz * Dz + d;
    const float* kp = Kt + (size_t)b * HWz * Dz + d;

    // pass 1: softmax over H for each w (in place)
    for (int w = 0; w < Wz; w++) {
        float v[Hz];
        float mx = -1e30f;
        #pragma unroll
        for (int h = 0; h < Hz; h++) { v[h] = r[(h * Wz + w) * Dz]; mx = fmaxf(mx, v[h]); }
        float s = 0.f;
        #pragma unroll
        for (int h = 0; h < Hz; h++) { v[h] = expf(v[h] - mx); s += v[h]; }
        float inv = 1.f / s;
        #pragma unroll
        for (int h = 0; h < Hz; h++) r[(h * Wz + w) * Dz] = v[h] * inv;
    }
    // pass 2: softmax over W of those probs, fused with ri reduction
    float acc = 0.f;
    for (int h = 0; h < Hz; h++) {
        float v[Wz];
        float mx = -1e30f;
        #pragma unroll
        for (int w = 0; w < Wz; w++) { v[w] = r[(h * Wz + w) * Dz]; mx = fmaxf(mx, v[w]); }
        float s = 0.f;
        #pragma unroll
        for (int w = 0; w < Wz; w++) { v[w] = expf(v[w] - mx); s += v[w]; }
        float inv = 1.f / s;
        #pragma unroll
        for (int w = 0; w < Wz; w++) acc += v[w] * inv * kp[(h * Wz + w) * Dz];
    }
    g_ri[b * Dz + d] = acc;
}

// ---------------- write attention: saij softmax over T, mi_sa = sum_t sa*M_past ----------------
__global__ void __launch_bounds__(512) sa_kernel(const float* __restrict__ C_past,
                                                 const float* __restrict__ M_past,
                                                 const float* __restrict__ Wwcc)
{
    int b = blockIdx.x, tid = threadIdx.x;  // 512
    int lane = tid & 31, warp = tid >> 5;   // 16 warps
    __shared__ float z[16];
    __shared__ float wsm[Tz];
    if (warp < Tz) {
        const float* cp = C_past + ((size_t)b * Tz + warp) * Dz;
        const float* cb = g_ci + b * Dz;
        float sum = 0.f;
        #pragma unroll 4
        for (int d = lane; d < Dz; d += 32) sum += cb[d] * cp[d] * Wwcc[d];
        #pragma unroll
        for (int o = 16; o; o >>= 1) sum += __shfl_xor_sync(0xffffffffu, sum, o);
        if (lane == 0) z[warp] = sum;
    }
    __syncthreads();
    if (tid == 0) {
        float mx = -1e30f;
        for (int t = 0; t < Tz; t++) mx = fmaxf(mx, z[t]);
        float s = 0.f;
        for (int t = 0; t < Tz; t++) { float e = expf(z[t] - mx); wsm[t] = e; s += e; }
        float inv = 1.f / s;
        for (int t = 0; t < Tz; t++) wsm[t] *= inv;
    }
    __syncthreads();
    float acc = 0.f;
    #pragma unroll
    for (int t = 0; t < Tz; t++)
        acc += wsm[t] * M_past[((size_t)b * Tz + t) * Dz + tid];
    g_mi_sa[b * Dz + tid] = acc;
}

// ---------------- gate + final output (ci, mi) ----------------
__global__ void __launch_bounds__(512) final_kernel(const float* __restrict__ mi_1,
                                                    const float* __restrict__ Wwci,
                                                    const float* __restrict__ bwci,
                                                    float* __restrict__ out)
{
    int b = blockIdx.x, tid = threadIdx.x;  // 512
    __shared__ float red[16];
    __shared__ float gsh;
    float civ = g_ci[b * Dz + tid];
    float sum = civ * Wwci[tid];
    #pragma unroll
    for (int o = 16; o; o >>= 1) sum += __shfl_xor_sync(0xffffffffu, sum, o);
    if ((tid & 31) == 0) red[tid >> 5] = sum;
    __syncthreads();
    if (tid < 32) {
        float v = (tid < 16) ? red[tid] : 0.f;
        #pragma unroll
        for (int o = 8; o; o >>= 1) v += __shfl_xor_sync(0xffffffffu, v, o);
        if (tid == 0) gsh = 1.f / (1.f + expf(-(v + bwci[0])));
    }
    __syncthreads();
    float g = gsh;
    float mi = g * mi_1[b * Dz + tid] + (1.f - g) * g_mi_prime[b * Dz + tid];
    out[b * Dz + tid] = civ;
    out[(size_t)Bz * Dz + b * Dz + tid] = mi;
}

// ---------------- launch ----------------
extern "C" void kernel_launch(void* const* d_in, const int* in_sizes, int n_in,
                              void* d_out, int out_size)
{
    const float* ci_1   = (const float*)d_in[0];
    const float* mi_1   = (const float*)d_in[1];
    const float* q      = (const float*)d_in[2];
    const float* cws    = (const float*)d_in[3];
    const float* Kt     = (const float*)d_in[4];
    const float* C_past = (const float*)d_in[5];
    const float* M_past = (const float*)d_in[6];
    const float* W_cq   = (const float*)d_in[7];
    const float* b_cq   = (const float*)d_in[8];
    const float* W_cqi  = (const float*)d_in[9];
    const float* b_cqi  = (const float*)d_in[10];
    const float* W_cai  = (const float*)d_in[11];
    const float* W_rm   = (const float*)d_in[13];
    const float* b_rm   = (const float*)d_in[14];
    const float* W_rk   = (const float*)d_in[15];
    const float* b_rk   = (const float*)d_in[16];
    const float* W_rik  = (const float*)d_in[17];
    const float* b_rik  = (const float*)d_in[18];
    const float* W_rci  = (const float*)d_in[19];
    const float* b_rci  = (const float*)d_in[20];
    const float* W_wrm  = (const float*)d_in[21];
    const float* b_wrm  = (const float*)d_in[22];
    const float* W_wcc  = (const float*)d_in[23];
    const float* W_wsa  = (const float*)d_in[25];
    const float* b_wsa  = (const float*)d_in[26];
    const float* W_winfo= (const float*)d_in[27];
    const float* b_winfo= (const float*)d_in[28];
    const float* W_wci  = (const float*)d_in[29];
    const float* b_wci  = (const float*)d_in[30];
    float* out = (float*)d_out;

    float *qi, *cqi, *ci, *rm, *rk, *ip, *rai, *ri, *mi_info, *mi_sa, *mi_prime;
    cudaGetSymbolAddress((void**)&qi, g_qi);
    cudaGetSymbolAddress((void**)&cqi, g_cqi);
    cudaGetSymbolAddress((void**)&ci, g_ci);
    cudaGetSymbolAddress((void**)&rm, g_rm);
    cudaGetSymbolAddress((void**)&rk, g_rk);
    cudaGetSymbolAddress((void**)&ip, g_ip);
    cudaGetSymbolAddress((void**)&rai, g_rai);
    cudaGetSymbolAddress((void**)&ri, g_ri);
    cudaGetSymbolAddress((void**)&mi_info, g_mi_info);
    cudaGetSymbolAddress((void**)&mi_sa, g_mi_sa);
    cudaGetSymbolAddress((void**)&mi_prime, g_mi_prime);

    dim3 gs(Dz / 128, Bz / 128);    // (4, 2)   small GEMMs M=256
    dim3 gb(Dz / 128, Mbig / 128);  // (4, 392) big GEMMs M=50176

    // ---- control ----
    sgemm_kernel<<<gs, 256>>>(q, W_cq, b_cq, qi, Bz, Dz, Dz, nullptr, 1, 0);
    sgemm_kernel<<<gs, 256>>>(ci_1, W_cqi, b_cqi, cqi, Bz, Dz, Dz, nullptr, 1, 0);
    sgemm_kernel<<<gs, 256>>>(qi, W_cqi + Dz * Dz, nullptr, cqi, Bz, Dz, Dz, nullptr, 1, 1);
    cai_kernel<<<(Bz * Sz) / 8, 256>>>(cws, W_cai);
    ci_kernel<<<Bz, 128>>>(cws);

    // ---- read ----
    sgemm_kernel<<<gs, 256>>>(mi_1, W_rm, b_rm, rm, Bz, Dz, Dz, nullptr, 1, 0);
    sgemm_kernel<<<gb, 256>>>(Kt, W_rk, b_rk, rk, Mbig, Dz, Dz, nullptr, 1, 0);
    // Ii' = (rm ⊙ rk) @ W_rik[:D] + K @ W_rik[D:] + b_rik   (scale folded into A load)
    sgemm_kernel<<<gb, 256>>>(rk, W_rik, b_rik, ip, Mbig, Dz, Dz, rm, HWz, 0);
    sgemm_kernel<<<gb, 256>>>(Kt, W_rik + Dz * Dz, nullptr, ip, Mbig, Dz, Dz, nullptr, 1, 1);
    // rai = (ci ⊙ Ii') @ W_rci + b_rci
    sgemm_kernel<<<gb, 256>>>(ip, W_rci, b_rci, rai, Mbig, Dz, Dz, ci, HWz, 0);
    rsoft_kernel<<<Bz, Dz>>>(Kt);

    // ---- write ----
    sgemm_kernel<<<gs, 256>>>(ri, W_wrm, b_wrm, mi_info, Bz, Dz, Dz, nullptr, 1, 0);
    sgemm_kernel<<<gs, 256>>>(mi_1, W_wrm + Dz * Dz, nullptr, mi_info, Bz, Dz, Dz, nullptr, 1, 1);
    sa_kernel<<<Bz, 512>>>(C_past, M_past, W_wcc);
    sgemm_kernel<<<gs, 256>>>(mi_sa, W_wsa, b_wsa, mi_prime, Bz, Dz, Dz, nullptr, 1, 0);
    sgemm_kernel<<<gs, 256>>>(mi_info, W_winfo, b_winfo, mi_prime, Bz, Dz, Dz, nullptr, 1, 1);
    final_kernel<<<Bz, 512>>>(mi_1, W_wci, b_wci, out);
}

// round 2
// speedup vs baseline: 1.2107x; 1.2107x over previous
#include <cuda_runtime.h>
#include <math.h>

#define Bz 256
#define Sz 128
#define Hz 14
#define Wz 14
#define Tz 12
#define Dz 512
#define HWz (Hz*Wz)
#define Mbig (Bz*HWz)   // 50176

// ---------------- scratch (device globals; no allocation) ----------------
__device__ float g_qi[Bz*Dz];
__device__ float g_cqi[Bz*Dz];
__device__ float g_cai[Bz*Sz];
__device__ float g_ci[Bz*Dz];
__device__ float g_rm[Bz*Dz];
__device__ float g_rk[(size_t)Mbig*Dz];
__device__ float g_ip[(size_t)Mbig*Dz];
__device__ float g_rai[(size_t)Mbig*Dz];
__device__ float g_ri[Bz*Dz];
__device__ float g_mi_info[Bz*Dz];
__device__ float g_mi_sa[Bz*Dz];
__device__ float g_mi_prime[Bz*Dz];

// ================= tf32 tensor-core GEMM =================
// C[M, 512] = Acat[M, Ktot] @ Bw[Ktot, 512] + bias
// Acat[m,k] = (k < K1) ? A1[m,k] * (scale1 ? scale1[(m/rpb)*512 + k] : 1)
//                      : A2[m, k-K1]          (A2 row stride = 512)
__device__ __forceinline__ unsigned f2tf(float f) {
    unsigned u;
    asm("cvt.rna.tf32.f32 %0, %1;" : "=r"(u) : "f"(f));
    return u;
}

__global__ void __launch_bounds__(256) tf32_gemm_kernel(
    const float* __restrict__ A1, const float* __restrict__ scale1,
    const float* __restrict__ A2, const float* __restrict__ Bw,
    const float* __restrict__ bias, float* __restrict__ C,
    int M, int K1, int Ktot, int rpb)
{
    __shared__ float As[128][36];   // [m][k], stride 36: frag LDS conflict-free
    __shared__ float Bs[32][136];   // [k][n], stride 136: frag LDS conflict-free

    const int tid  = threadIdx.x;
    const int m0   = blockIdx.y * 128;
    const int n0   = blockIdx.x * 128;
    const int warp = tid >> 5;
    const int lane = tid & 31;
    const int wm = warp >> 2;       // 0..1  (64 rows each)
    const int wn = warp & 3;        // 0..3  (32 cols each)
    const int g  = lane >> 2;       // 0..7
    const int t  = lane & 3;        // 0..3

    float acc[4][4][4];
    #pragma unroll
    for (int i = 0; i < 4; i++)
        #pragma unroll
        for (int j = 0; j < 4; j++)
            #pragma unroll
            for (int c = 0; c < 4; c++) acc[i][j][c] = 0.f;

    for (int kt = 0; kt < Ktot; kt += 32) {
        // ---- load A tile 128x32 ----
        #pragma unroll
        for (int i = 0; i < 4; i++) {
            int f4  = tid + i * 256;
            int row = f4 >> 3;
            int c4  = (f4 & 7) << 2;
            int m   = m0 + row;
            int kg  = kt + c4;
            float4 a;
            if (kg < K1) {
                a = *(const float4*)(A1 + (size_t)m * K1 + kg);
                if (scale1) {
                    float4 s = *(const float4*)(scale1 + (size_t)(m / rpb) * Dz + kg);
                    a.x *= s.x; a.y *= s.y; a.z *= s.z; a.w *= s.w;
                }
            } else {
                a = *(const float4*)(A2 + (size_t)m * 512 + (kg - K1));
            }
            uint4 u = make_uint4(f2tf(a.x), f2tf(a.y), f2tf(a.z), f2tf(a.w));
            *(uint4*)&As[row][c4] = u;
        }
        // ---- load B tile 32x128 ----
        #pragma unroll
        for (int i = 0; i < 4; i++) {
            int f4   = tid + i * 256;
            int brow = f4 >> 5;
            int bc4  = (f4 & 31) << 2;
            float4 b = *(const float4*)(Bw + (size_t)(kt + brow) * Dz + n0 + bc4);
            uint4 u = make_uint4(f2tf(b.x), f2tf(b.y), f2tf(b.z), f2tf(b.w));
            *(uint4*)&Bs[brow][bc4] = u;
        }
        __syncthreads();

        #pragma unroll
        for (int ks = 0; ks < 4; ks++) {
            const int kb = ks << 3;
            unsigned bf[4][2];
            #pragma unroll
            for (int an = 0; an < 4; an++) {
                int col = wn * 32 + an * 8 + g;
                bf[an][0] = __float_as_uint(Bs[kb + t][col]);
                bf[an][1] = __float_as_uint(Bs[kb + t + 4][col]);
            }
            #pragma unroll
            for (int am = 0; am < 4; am++) {
                int rb = wm * 64 + am * 16;
                unsigned a0 = __float_as_uint(As[rb + g][kb + t]);
                unsigned a1 = __float_as_uint(As[rb + g + 8][kb + t]);
                unsigned a2 = __float_as_uint(As[rb + g][kb + t + 4]);
                unsigned a3 = __float_as_uint(As[rb + g + 8][kb + t + 4]);
                #pragma unroll
                for (int an = 0; an < 4; an++) {
                    asm volatile(
                        "mma.sync.aligned.m16n8k8.row.col.f32.tf32.tf32.f32 "
                        "{%0,%1,%2,%3}, {%4,%5,%6,%7}, {%8,%9}, {%0,%1,%2,%3};"
                        : "+f"(acc[am][an][0]), "+f"(acc[am][an][1]),
                          "+f"(acc[am][an][2]), "+f"(acc[am][an][3])
                        : "r"(a0), "r"(a1), "r"(a2), "r"(a3),
                          "r"(bf[an][0]), "r"(bf[an][1]));
                }
            }
        }
        __syncthreads();
    }

    // ---- epilogue ----
    #pragma unroll
    for (int am = 0; am < 4; am++) {
        int r0 = m0 + wm * 64 + am * 16 + g;
        #pragma unroll
        for (int an = 0; an < 4; an++) {
            int col = n0 + wn * 32 + an * 8 + t * 2;
            float b0 = bias[col], b1 = bias[col + 1];
            float2 v0 = make_float2(acc[am][an][0] + b0, acc[am][an][1] + b1);
            float2 v1 = make_float2(acc[am][an][2] + b0, acc[am][an][3] + b1);
            *(float2*)(C + (size_t)r0 * Dz + col) = v0;
            *(float2*)(C + (size_t)(r0 + 8) * Dz + col) = v1;
        }
    }
}

// ---------------- generic fp32 SGEMM (small M=256 GEMMs) ----------------
__global__ void __launch_bounds__(256) sgemm_kernel(
    const float* __restrict__ A, const float* __restrict__ Bw,
    const float* __restrict__ bias, float* __restrict__ C,
    int M, int N, int K,
    const float* __restrict__ scale, int rpb, int acc_flag)
{
    __shared__ float As[8][128];
    __shared__ float Bs[8][128];
    const int tid = threadIdx.x;
    const int m0 = blockIdx.y * 128;
    const int n0 = blockIdx.x * 128;
    const int tx = tid & 15;
    const int ty = tid >> 4;

    const int aRow = tid >> 1;
    const int aCol = (tid & 1) << 2;
    const int bRow = tid >> 5;
    const int bCol = (tid & 31) << 2;

    float acc[8][8];
    #pragma unroll
    for (int i = 0; i < 8; i++)
        #pragma unroll
        for (int j = 0; j < 8; j++) acc[i][j] = 0.f;

    const float* Aptr = A + (size_t)(m0 + aRow) * K + aCol;
    const float* Sptr = nullptr;
    if (scale) Sptr = scale + (size_t)((m0 + aRow) / rpb) * K + aCol;

    for (int kt = 0; kt < K; kt += 8) {
        float4 a = *(const float4*)(Aptr + kt);
        if (Sptr) {
            float4 s = *(const float4*)(Sptr + kt);
            a.x *= s.x; a.y *= s.y; a.z *= s.z; a.w *= s.w;
        }
        As[aCol + 0][aRow] = a.x;
        As[aCol + 1][aRow] = a.y;
        As[aCol + 2][aRow] = a.z;
        As[aCol + 3][aRow] = a.w;

        float4 b = *(const float4*)(Bw + (size_t)(kt + bRow) * N + n0 + bCol);
        *(float4*)&Bs[bRow][bCol] = b;
        __syncthreads();

        #pragma unroll
        for (int k = 0; k < 8; k++) {
            float ar[8], br[8];
            #pragma unroll
            for (int i = 0; i < 8; i++) ar[i] = As[k][ty * 8 + i];
            #pragma unroll
            for (int j = 0; j < 8; j++) br[j] = Bs[k][tx * 8 + j];
            #pragma unroll
            for (int i = 0; i < 8; i++)
                #pragma unroll
                for (int j = 0; j < 8; j++)
                    acc[i][j] = fmaf(ar[i], br[j], acc[i][j]);
        }
        __syncthreads();
    }

    #pragma unroll
    for (int i = 0; i < 8; i++) {
        int row = m0 + ty * 8 + i;
        float* crow = C + (size_t)row * N + n0 + tx * 8;
        #pragma unroll
        for (int j = 0; j < 8; j++) {
            float v = acc[i][j];
            if (bias) v += bias[n0 + tx * 8 + j];
            if (acc_flag) v += crow[j];
            crow[j] = v;
        }
    }
}

// ---------------- cai[b,s] = sum_d cqi[b,d]*cws[b,s,d]*W_cai[d] ----------------
__global__ void __launch_bounds__(256) cai_kernel(const float* __restrict__ cws,
                                                  const float* __restrict__ Wcai)
{
    int warp = (blockIdx.x * blockDim.x + threadIdx.x) >> 5;
    int lane = threadIdx.x & 31;
    if (warp >= Bz * Sz) return;
    int b = warp / Sz;
    const float* cq = g_cqi + b * Dz;
    const float* cw = cws + (size_t)warp * Dz;
    float sum = 0.f;
    #pragma unroll 4
    for (int d = lane; d < Dz; d += 32)
        sum += cq[d] * cw[d] * Wcai[d];
    #pragma unroll
    for (int o = 16; o; o >>= 1) sum += __shfl_xor_sync(0xffffffffu, sum, o);
    if (lane == 0) g_cai[warp] = sum;
}

// ---------------- softmax over S + ci reduction ----------------
__global__ void __launch_bounds__(128) ci_kernel(const float* __restrict__ cws)
{
    int b = blockIdx.x, tid = threadIdx.x;
    __shared__ float wsm[Sz];
    __shared__ float red[4];
    float x = g_cai[b * Sz + tid];
    float m = x;
    #pragma unroll
    for (int o = 16; o; o >>= 1) m = fmaxf(m, __shfl_xor_sync(0xffffffffu, m, o));
    if ((tid & 31) == 0) red[tid >> 5] = m;
    __syncthreads();
    float bm = fmaxf(fmaxf(red[0], red[1]), fmaxf(red[2], red[3]));
    __syncthreads();
    float e = expf(x - bm);
    float s = e;
    #pragma unroll
    for (int o = 16; o; o >>= 1) s += __shfl_xor_sync(0xffffffffu, s, o);
    if ((tid & 31) == 0) red[tid >> 5] = s;
    __syncthreads();
    float bs = red[0] + red[1] + red[2] + red[3];
    wsm[tid] = e / bs;
    __syncthreads();
    for (int d = tid; d < Dz; d += 128) {
        float acc = 0.f;
        #pragma unroll 8
        for (int s2 = 0; s2 < Sz; s2++)
            acc += wsm[s2] * cws[((size_t)b * Sz + s2) * Dz + d];
        g_ci[b * Dz + d] = acc;
    }
}

// ---------------- double softmax + ri ----------------
__global__ void __launch_bounds__(512) rsoft_kernel(const float* __restrict__ Kt)
{
    int b = blockIdx.x;
    int d = threadIdx.x;
    float* r = g_rai + (size_t)b * HWz * Dz + d;
    const float* kp = Kt + (size_t)b * HWz * Dz + d;

    for (int w = 0; w < Wz; w++) {
        float v[Hz];
        float mx = -1e30f;
        #pragma unroll
        for (int h = 0; h < Hz; h++) { v[h] = r[(h * Wz + w) * Dz]; mx = fmaxf(mx, v[h]); }
        float s = 0.f;
        #pragma unroll
        for (int h = 0; h < Hz; h++) { v[h] = expf(v[h] - mx); s += v[h]; }
        float inv = 1.f / s;
        #pragma unroll
        for (int h = 0; h < Hz; h++) r[(h * Wz + w) * Dz] = v[h] * inv;
    }
    float acc = 0.f;
    for (int h = 0; h < Hz; h++) {
        float v[Wz];
        float mx = -1e30f;
        #pragma unroll
        for (int w = 0; w < Wz; w++) { v[w] = r[(h * Wz + w) * Dz]; mx = fmaxf(mx, v[w]); }
        float s = 0.f;
        #pragma unroll
        for (int w = 0; w < Wz; w++) { v[w] = expf(v[w] - mx); s += v[w]; }
        float inv = 1.f / s;
        #pragma unroll
        for (int w = 0; w < Wz; w++) acc += v[w] * inv * kp[(h * Wz + w) * Dz];
    }
    g_ri[b * Dz + d] = acc;
}

// ---------------- write attention ----------------
__global__ void __launch_bounds__(512) sa_kernel(const float* __restrict__ C_past,
                                                 const float* __restrict__ M_past,
                                                 const float* __restrict__ Wwcc)
{
    int b = blockIdx.x, tid = threadIdx.x;
    int lane = tid & 31, warp = tid >> 5;
    __shared__ float z[16];
    __shared__ float wsm[Tz];
    if (warp < Tz) {
        const float* cp = C_past + ((size_t)b * Tz + warp) * Dz;
        const float* cb = g_ci + b * Dz;
        float sum = 0.f;
        #pragma unroll 4
        for (int d = lane; d < Dz; d += 32) sum += cb[d] * cp[d] * Wwcc[d];
        #pragma unroll
        for (int o = 16; o; o >>= 1) sum += __shfl_xor_sync(0xffffffffu, sum, o);
        if (lane == 0) z[warp] = sum;
    }
    __syncthreads();
    if (tid == 0) {
        float mx = -1e30f;
        for (int t = 0; t < Tz; t++) mx = fmaxf(mx, z[t]);
        float s = 0.f;
        for (int t = 0; t < Tz; t++) { float e = expf(z[t] - mx); wsm[t] = e; s += e; }
        float inv = 1.f / s;
        for (int t = 0; t < Tz; t++) wsm[t] *= inv;
    }
    __syncthreads();
    float acc = 0.f;
    #pragma unroll
    for (int t = 0; t < Tz; t++)
        acc += wsm[t] * M_past[((size_t)b * Tz + t) * Dz + tid];
    g_mi_sa[b * Dz + tid] = acc;
}

// ---------------- gate + final ----------------
__global__ void __launch_bounds__(512) final_kernel(const float* __restrict__ mi_1,
                                                    const float* __restrict__ Wwci,
                                                    const float* __restrict__ bwci,
                                                    float* __restrict__ out)
{
    int b = blockIdx.x, tid = threadIdx.x;
    __shared__ float red[16];
    __shared__ float gsh;
    float civ = g_ci[b * Dz + tid];
    float sum = civ * Wwci[tid];
    #pragma unroll
    for (int o = 16; o; o >>= 1) sum += __shfl_xor_sync(0xffffffffu, sum, o);
    if ((tid & 31) == 0) red[tid >> 5] = sum;
    __syncthreads();
    if (tid < 32) {
        float v = (tid < 16) ? red[tid] : 0.f;
        #pragma unroll
        for (int o = 8; o; o >>= 1) v += __shfl_xor_sync(0xffffffffu, v, o);
        if (tid == 0) gsh = 1.f / (1.f + expf(-(v + bwci[0])));
    }
    __syncthreads();
    float g = gsh;
    float mi = g * mi_1[b * Dz + tid] + (1.f - g) * g_mi_prime[b * Dz + tid];
    out[b * Dz + tid] = civ;
    out[(size_t)Bz * Dz + b * Dz + tid] = mi;
}

// ---------------- launch ----------------
extern "C" void kernel_launch(void* const* d_in, const int* in_sizes, int n_in,
                              void* d_out, int out_size)
{
    const float* ci_1   = (const float*)d_in[0];
    const float* mi_1   = (const float*)d_in[1];
    const float* q      = (const float*)d_in[2];
    const float* cws    = (const float*)d_in[3];
    const float* Kt     = (const float*)d_in[4];
    const float* C_past = (const float*)d_in[5];
    const float* M_past = (const float*)d_in[6];
    const float* W_cq   = (const float*)d_in[7];
    const float* b_cq   = (const float*)d_in[8];
    const float* W_cqi  = (const float*)d_in[9];
    const float* b_cqi  = (const float*)d_in[10];
    const float* W_cai  = (const float*)d_in[11];
    const float* W_rm   = (const float*)d_in[13];
    const float* b_rm   = (const float*)d_in[14];
    const float* W_rk   = (const float*)d_in[15];
    const float* b_rk   = (const float*)d_in[16];
    const float* W_rik  = (const float*)d_in[17];
    const float* b_rik  = (const float*)d_in[18];
    const float* W_rci  = (const float*)d_in[19];
    const float* b_rci  = (const float*)d_in[20];
    const float* W_wrm  = (const float*)d_in[21];
    const float* b_wrm  = (const float*)d_in[22];
    const float* W_wcc  = (const float*)d_in[23];
    const float* W_wsa  = (const float*)d_in[25];
    const float* b_wsa  = (const float*)d_in[26];
    const float* W_winfo= (const float*)d_in[27];
    const float* b_winfo= (const float*)d_in[28];
    const float* W_wci  = (const float*)d_in[29];
    const float* b_wci  = (const float*)d_in[30];
    float* out = (float*)d_out;

    float *qi, *cqi, *ci, *rm, *rk, *ip, *rai, *ri, *mi_info, *mi_sa, *mi_prime;
    cudaGetSymbolAddress((void**)&qi, g_qi);
    cudaGetSymbolAddress((void**)&cqi, g_cqi);
    cudaGetSymbolAddress((void**)&ci, g_ci);
    cudaGetSymbolAddress((void**)&rm, g_rm);
    cudaGetSymbolAddress((void**)&rk, g_rk);
    cudaGetSymbolAddress((void**)&ip, g_ip);
    cudaGetSymbolAddress((void**)&rai, g_rai);
    cudaGetSymbolAddress((void**)&ri, g_ri);
    cudaGetSymbolAddress((void**)&mi_info, g_mi_info);
    cudaGetSymbolAddress((void**)&mi_sa, g_mi_sa);
    cudaGetSymbolAddress((void**)&mi_prime, g_mi_prime);

    dim3 gs(Dz / 128, Bz / 128);    // small GEMMs M=256
    dim3 gb(Dz / 128, Mbig / 128);  // big GEMMs M=50176

    // ---- control (fp32 for accuracy of ci path) ----
    sgemm_kernel<<<gs, 256>>>(q, W_cq, b_cq, qi, Bz, Dz, Dz, nullptr, 1, 0);
    sgemm_kernel<<<gs, 256>>>(ci_1, W_cqi, b_cqi, cqi, Bz, Dz, Dz, nullptr, 1, 0);
    sgemm_kernel<<<gs, 256>>>(qi, W_cqi + Dz * Dz, nullptr, cqi, Bz, Dz, Dz, nullptr, 1, 1);
    cai_kernel<<<(Bz * Sz) / 8, 256>>>(cws, W_cai);
    ci_kernel<<<Bz, 128>>>(cws);

    // ---- read (tensor-core tf32 for the big GEMMs) ----
    sgemm_kernel<<<gs, 256>>>(mi_1, W_rm, b_rm, rm, Bz, Dz, Dz, nullptr, 1, 0);
    // rk = K @ W_rk + b_rk
    tf32_gemm_kernel<<<gb, 256>>>(Kt, nullptr, nullptr, W_rk, b_rk, rk, Mbig, Dz, Dz, 1);
    // ip = concat(rm⊙rk, K) @ W_rik + b_rik   (single fused Ktot=1024 GEMM)
    tf32_gemm_kernel<<<gb, 256>>>(rk, rm, Kt, W_rik, b_rik, ip, Mbig, Dz, 2 * Dz, HWz);
    // rai = (ci⊙ip) @ W_rci + b_rci
    tf32_gemm_kernel<<<gb, 256>>>(ip, ci, nullptr, W_rci, b_rci, rai, Mbig, Dz, Dz, HWz);
    rsoft_kernel<<<Bz, Dz>>>(Kt);

    // ---- write (fp32) ----
    sgemm_kernel<<<gs, 256>>>(ri, W_wrm, b_wrm, mi_info, Bz, Dz, Dz, nullptr, 1, 0);
    sgemm_kernel<<<gs, 256>>>(mi_1, W_wrm + Dz * Dz, nullptr, mi_info, Bz, Dz, Dz, nullptr, 1, 1);
    sa_kernel<<<Bz, 512>>>(C_past, M_past, W_wcc);
    sgemm_kernel<<<gs, 256>>>(mi_sa, W_wsa, b_wsa, mi_prime, Bz, Dz, Dz, nullptr, 1, 0);
    sgemm_kernel<<<gs, 256>>>(mi_info, W_winfo, b_winfo, mi_prime, Bz, Dz, Dz, nullptr, 1, 1);
    final_kernel<<<Bz, 512>>>(mi_1, W_wci, b_wci, out);
}

// round 8
// speedup vs baseline: 2.5620x; 2.1162x over previous
#include <cuda_runtime.h>
#include <cuda_bf16.h>
#include <stdint.h>
#include <math.h>

#define Bz 256
#define Sz 128
#define Hz 14
#define Wz 14
#define Tz 12
#define Dz 512
#define HWz (Hz*Wz)
#define Mbig (Bz*HWz)   // 50176

// ---------------- scratch (device globals; no allocation) ----------------
__device__ float g_qi[Bz*Dz];
__device__ float g_cqi[Bz*Dz];
__device__ float g_cai[Bz*Sz];
__device__ float g_ci[Bz*Dz];
__device__ float g_rm[Bz*Dz];
__device__ float g_ri[Bz*Dz];
__device__ float g_mi_info[Bz*Dz];
__device__ float g_mi_sa[Bz*Dz];
__device__ float g_mi_prime[Bz*Dz];
__device__ float g_rai[(size_t)Mbig*Dz];
__device__ __nv_bfloat16 g_K_bf[(size_t)Mbig*Dz];
__device__ __nv_bfloat16 g_rk_bf[(size_t)Mbig*Dz];   // holds rm ⊙ (K@W_rk + b_rk)
__device__ __nv_bfloat16 g_ip_bf[(size_t)Mbig*Dz];   // holds ci ⊙ (concat@W_rik + b_rik)
__device__ __nv_bfloat16 g_Wt_rk[Dz*Dz];
__device__ __nv_bfloat16 g_Wt_rik[2*Dz*Dz];
__device__ __nv_bfloat16 g_Wt_rci[Dz*Dz];

// ================= helpers =================
__device__ __forceinline__ uint32_t smem_u32(const void* p) {
    uint32_t a;
    asm("{ .reg .u64 t; cvta.to.shared.u64 t, %1; cvt.u32.u64 %0, t; }" : "=r"(a) : "l"(p));
    return a;
}
__device__ __forceinline__ void cp16(uint32_t dst, const void* src) {
    asm volatile("cp.async.cg.shared.global [%0], [%1], 16;" :: "r"(dst), "l"(src) : "memory");
}
__device__ __forceinline__ void mma_bf16(float* c, uint32_t a0, uint32_t a1,
                                         uint32_t a2, uint32_t a3,
                                         uint32_t b0, uint32_t b1) {
    asm volatile("mma.sync.aligned.m16n8k16.row.col.f32.bf16.bf16.f32 "
        "{%0,%1,%2,%3}, {%4,%5,%6,%7}, {%8,%9}, {%0,%1,%2,%3};"
        : "+f"(c[0]), "+f"(c[1]), "+f"(c[2]), "+f"(c[3])
        : "r"(a0), "r"(a1), "r"(a2), "r"(a3), "r"(b0), "r"(b1));
}

#define TSTRIDE 80           // bytes per smem tile row (32 bf16 + 8 pad)
#define TILE_BYTES (128*TSTRIDE)   // 10240
#define HG_SMEM (4*TILE_BYTES)     // 40960 (A0,A1,B0,B1)

// ================= bf16 HMMA GEMM =================
// C[M,512] = Acat[M,Ktot] @ W[Ktot,512] + bias, then optional (⊙ scale[row/196, col])
// Acat[m,k] = (k<K1) ? A1[m,k] : A2[m,k-K1]   (A2 row stride 512, bf16)
// Bt = W^T bf16, [512][Ktot] row-major.
__global__ void __launch_bounds__(256, 2) hgemm_kernel(
    const __nv_bfloat16* __restrict__ A1,
    const __nv_bfloat16* __restrict__ A2,
    const __nv_bfloat16* __restrict__ Bt,
    const float* __restrict__ bias,
    const float* __restrict__ scale,
    void* __restrict__ Cout, int c_is_bf16,
    int K1, int Ktot)
{
    extern __shared__ char sm[];
    char* buf[4] = { sm, sm + TILE_BYTES, sm + 2*TILE_BYTES, sm + 3*TILE_BYTES }; // A0 A1 B0 B1

    const int tid  = threadIdx.x;
    const int m0   = blockIdx.x * 128;
    const int n0   = blockIdx.y * 128;
    const int warp = tid >> 5;
    const int lane = tid & 31;
    const int wm = warp >> 2;        // 0..1 (64 rows)
    const int wn = warp & 3;         // 0..3 (32 cols)
    const int g  = lane >> 2;        // 0..7
    const int t  = lane & 3;         // 0..3

    float acc[4][4][4];
    #pragma unroll
    for (int i = 0; i < 4; i++)
        #pragma unroll
        for (int j = 0; j < 4; j++)
            #pragma unroll
            for (int k = 0; k < 4; k++) acc[i][j][k] = 0.f;

    const int nch = Ktot >> 5;

    // tile loader: chunk = 512 x 16B per operand; 256 threads x 2 x (A+B)
    auto load_tile = [&](int c) {
        const int kt = c << 5;
        const int s = c & 1;
        uint32_t ab = smem_u32(buf[s]);
        uint32_t bb = smem_u32(buf[2 + s]);
        #pragma unroll
        for (int i = 0; i < 2; i++) {
            int chunk = tid + (i << 8);
            int row = chunk >> 2, cc = chunk & 3;
            int kg = kt + (cc << 3);
            const __nv_bfloat16* sa = (kg < K1)
                ? (A1 + (size_t)(m0 + row) * K1 + kg)
                : (A2 + (size_t)(m0 + row) * Dz + (kg - K1));
            cp16(ab + row * TSTRIDE + cc * 16, sa);
            cp16(bb + row * TSTRIDE + cc * 16,
                 Bt + (size_t)(n0 + row) * Ktot + kt + (cc << 3));
        }
        asm volatile("cp.async.commit_group;" ::: "memory");
    };

    load_tile(0);
    for (int c = 0; c < nch; c++) {
        if (c + 1 < nch) {
            load_tile(c + 1);
            asm volatile("cp.async.wait_group 1;" ::: "memory");
        } else {
            asm volatile("cp.async.wait_group 0;" ::: "memory");
        }
        __syncthreads();

        const char* ab = buf[c & 1];
        const char* bb = buf[2 + (c & 1)];
        #pragma unroll
        for (int ks = 0; ks < 2; ks++) {
            uint32_t bfr[4][2];
            #pragma unroll
            for (int an = 0; an < 4; an++) {
                const char* p = bb + (wn * 32 + an * 8 + g) * TSTRIDE + ks * 32 + t * 4;
                bfr[an][0] = *(const uint32_t*)p;
                bfr[an][1] = *(const uint32_t*)(p + 16);
            }
            #pragma unroll
            for (int am = 0; am < 4; am++) {
                const char* p = ab + (wm * 64 + am * 16 + g) * TSTRIDE + ks * 32 + t * 4;
                uint32_t a0 = *(const uint32_t*)p;
                uint32_t a2 = *(const uint32_t*)(p + 16);
                uint32_t a1 = *(const uint32_t*)(p + 8 * TSTRIDE);
                uint32_t a3 = *(const uint32_t*)(p + 8 * TSTRIDE + 16);
                #pragma unroll
                for (int an = 0; an < 4; an++)
                    mma_bf16(acc[am][an], a0, a1, a2, a3, bfr[an][0], bfr[an][1]);
            }
        }
        __syncthreads();
    }

    // ---- epilogue: c0:(g,2t) c1:(g,2t+1) c2:(g+8,2t) c3:(g+8,2t+1) ----
    #pragma unroll
    for (int am = 0; am < 4; am++) {
        int r0 = m0 + wm * 64 + am * 16 + g;
        int r1 = r0 + 8;
        #pragma unroll
        for (int an = 0; an < 4; an++) {
            int col = n0 + wn * 32 + an * 8 + t * 2;
            float b0 = bias[col], b1 = bias[col + 1];
            float v00 = acc[am][an][0] + b0, v01 = acc[am][an][1] + b1;
            float v10 = acc[am][an][2] + b0, v11 = acc[am][an][3] + b1;
            if (scale) {
                const float* s0 = scale + (size_t)(r0 / HWz) * Dz + col;
                const float* s1 = scale + (size_t)(r1 / HWz) * Dz + col;
                v00 *= s0[0]; v01 *= s0[1];
                v10 *= s1[0]; v11 *= s1[1];
            }
            if (c_is_bf16) {
                union { __nv_bfloat162 h; uint32_t u; } p0, p1;
                p0.h = __floats2bfloat162_rn(v00, v01);
                p1.h = __floats2bfloat162_rn(v10, v11);
                *(uint32_t*)((__nv_bfloat16*)Cout + (size_t)r0 * Dz + col) = p0.u;
                *(uint32_t*)((__nv_bfloat16*)Cout + (size_t)r1 * Dz + col) = p1.u;
            } else {
                *(float2*)((float*)Cout + (size_t)r0 * Dz + col) = make_float2(v00, v01);
                *(float2*)((float*)Cout + (size_t)r1 * Dz + col) = make_float2(v10, v11);
            }
        }
    }
}

// ---------------- fp32 -> bf16 bulk convert ----------------
__global__ void __launch_bounds__(256) f2bf_kernel(const float* __restrict__ in,
                                                   __nv_bfloat16* __restrict__ out)
{
    size_t i = ((size_t)blockIdx.x * 256 + threadIdx.x) * 4;
    float4 v = *(const float4*)(in + i);
    union { __nv_bfloat162 h; uint32_t u; } p0, p1;
    p0.h = __floats2bfloat162_rn(v.x, v.y);
    p1.h = __floats2bfloat162_rn(v.z, v.w);
    *(uint2*)(out + i) = make_uint2(p0.u, p1.u);
}

// ---------------- weight transpose: Wt[n][k] = (bf16) W[k][n] ----------------
__global__ void __launch_bounds__(256) transpose_w_kernel(
    const float* __restrict__ W, __nv_bfloat16* __restrict__ Wt, int K, int N)
{
    __shared__ float t[32][33];
    int k0 = blockIdx.x * 32, n0 = blockIdx.y * 32;
    int x = threadIdx.x & 31, y = threadIdx.x >> 5;
    #pragma unroll
    for (int j = 0; j < 32; j += 8)
        t[y + j][x] = W[(size_t)(k0 + y + j) * N + n0 + x];
    __syncthreads();
    #pragma unroll
    for (int j = 0; j < 32; j += 8)
        Wt[(size_t)(n0 + y + j) * K + k0 + x] = __float2bfloat16(t[x][y + j]);
}

// ---------------- generic fp32 SGEMM (small M=256 GEMMs) ----------------
__global__ void __launch_bounds__(256) sgemm_kernel(
    const float* __restrict__ A, const float* __restrict__ Bw,
    const float* __restrict__ bias, float* __restrict__ C,
    int M, int N, int K,
    const float* __restrict__ scale, int rpb, int acc_flag)
{
    __shared__ float As[8][128];
    __shared__ float Bs[8][128];
    const int tid = threadIdx.x;
    const int m0 = blockIdx.y * 128;
    const int n0 = blockIdx.x * 128;
    const int tx = tid & 15;
    const int ty = tid >> 4;
    const int aRow = tid >> 1;
    const int aCol = (tid & 1) << 2;
    const int bRow = tid >> 5;
    const int bCol = (tid & 31) << 2;

    float acc[8][8];
    #pragma unroll
    for (int i = 0; i < 8; i++)
        #pragma unroll
        for (int j = 0; j < 8; j++) acc[i][j] = 0.f;

    const float* Aptr = A + (size_t)(m0 + aRow) * K + aCol;
    const float* Sptr = nullptr;
    if (scale) Sptr = scale + (size_t)((m0 + aRow) / rpb) * K + aCol;

    for (int kt = 0; kt < K; kt += 8) {
        float4 a = *(const float4*)(Aptr + kt);
        if (Sptr) {
            float4 s = *(const float4*)(Sptr + kt);
            a.x *= s.x; a.y *= s.y; a.z *= s.z; a.w *= s.w;
        }
        As[aCol + 0][aRow] = a.x;
        As[aCol + 1][aRow] = a.y;
        As[aCol + 2][aRow] = a.z;
        As[aCol + 3][aRow] = a.w;
        float4 b = *(const float4*)(Bw + (size_t)(kt + bRow) * N + n0 + bCol);
        *(float4*)&Bs[bRow][bCol] = b;
        __syncthreads();
        #pragma unroll
        for (int k = 0; k < 8; k++) {
            float ar[8], br[8];
            #pragma unroll
            for (int i = 0; i < 8; i++) ar[i] = As[k][ty * 8 + i];
            #pragma unroll
            for (int j = 0; j < 8; j++) br[j] = Bs[k][tx * 8 + j];
            #pragma unroll
            for (int i = 0; i < 8; i++)
                #pragma unroll
                for (int j = 0; j < 8; j++)
                    acc[i][j] = fmaf(ar[i], br[j], acc[i][j]);
        }
        __syncthreads();
    }
    #pragma unroll
    for (int i = 0; i < 8; i++) {
        int row = m0 + ty * 8 + i;
        float* crow = C + (size_t)row * N + n0 + tx * 8;
        #pragma unroll
        for (int j = 0; j < 8; j++) {
            float v = acc[i][j];
            if (bias) v += bias[n0 + tx * 8 + j];
            if (acc_flag) v += crow[j];
            crow[j] = v;
        }
    }
}

// ---------------- cai[b,s] = sum_d cqi[b,d]*cws[b,s,d]*W_cai[d] ----------------
__global__ void __launch_bounds__(256) cai_kernel(const float* __restrict__ cws,
                                                  const float* __restrict__ Wcai)
{
    int warp = (blockIdx.x * blockDim.x + threadIdx.x) >> 5;
    int lane = threadIdx.x & 31;
    if (warp >= Bz * Sz) return;
    int b = warp / Sz;
    const float* cq = g_cqi + b * Dz;
    const float* cw = cws + (size_t)warp * Dz;
    float sum = 0.f;
    #pragma unroll 4
    for (int d = lane; d < Dz; d += 32)
        sum += cq[d] * cw[d] * Wcai[d];
    #pragma unroll
    for (int o = 16; o; o >>= 1) sum += __shfl_xor_sync(0xffffffffu, sum, o);
    if (lane == 0) g_cai[warp] = sum;
}

// ---------------- softmax over S + ci reduction ----------------
__global__ void __launch_bounds__(128) ci_kernel(const float* __restrict__ cws)
{
    int b = blockIdx.x, tid = threadIdx.x;
    __shared__ float wsm[Sz];
    __shared__ float red[4];
    float x = g_cai[b * Sz + tid];
    float m = x;
    #pragma unroll
    for (int o = 16; o; o >>= 1) m = fmaxf(m, __shfl_xor_sync(0xffffffffu, m, o));
    if ((tid & 31) == 0) red[tid >> 5] = m;
    __syncthreads();
    float bm = fmaxf(fmaxf(red[0], red[1]), fmaxf(red[2], red[3]));
    __syncthreads();
    float e = expf(x - bm);
    float s = e;
    #pragma unroll
    for (int o = 16; o; o >>= 1) s += __shfl_xor_sync(0xffffffffu, s, o);
    if ((tid & 31) == 0) red[tid >> 5] = s;
    __syncthreads();
    float bs = red[0] + red[1] + red[2] + red[3];
    wsm[tid] = e / bs;
    __syncthreads();
    for (int d = tid; d < Dz; d += 128) {
        float acc = 0.f;
        #pragma unroll 8
        for (int s2 = 0; s2 < Sz; s2++)
            acc += wsm[s2] * cws[((size_t)b * Sz + s2) * Dz + d];
        g_ci[b * Dz + d] = acc;
    }
}

// ---------------- double softmax + ri ----------------
__global__ void __launch_bounds__(512) rsoft_kernel(const float* __restrict__ Kt)
{
    int b = blockIdx.x;
    int d = threadIdx.x;
    float* r = g_rai + (size_t)b * HWz * Dz + d;
    const float* kp = Kt + (size_t)b * HWz * Dz + d;

    for (int w = 0; w < Wz; w++) {
        float v[Hz];
        float mx = -1e30f;
        #pragma unroll
        for (int h = 0; h < Hz; h++) { v[h] = r[(h * Wz + w) * Dz]; mx = fmaxf(mx, v[h]); }
        float s = 0.f;
        #pragma unroll
        for (int h = 0; h < Hz; h++) { v[h] = expf(v[h] - mx); s += v[h]; }
        float inv = 1.f / s;
        #pragma unroll
        for (int h = 0; h < Hz; h++) r[(h * Wz + w) * Dz] = v[h] * inv;
    }
    float acc = 0.f;
    for (int h = 0; h < Hz; h++) {
        float v[Wz];
        float mx = -1e30f;
        #pragma unroll
        for (int w = 0; w < Wz; w++) { v[w] = r[(h * Wz + w) * Dz]; mx = fmaxf(mx, v[w]); }
        float s = 0.f;
        #pragma unroll
        for (int w = 0; w < Wz; w++) { v[w] = expf(v[w] - mx); s += v[w]; }
        float inv = 1.f / s;
        #pragma unroll
        for (int w = 0; w < Wz; w++) acc += v[w] * inv * kp[(h * Wz + w) * Dz];
    }
    g_ri[b * Dz + d] = acc;
}

// ---------------- write attention ----------------
__global__ void __launch_bounds__(512) sa_kernel(const float* __restrict__ C_past,
                                                 const float* __restrict__ M_past,
                                                 const float* __restrict__ Wwcc)
{
    int b = blockIdx.x, tid = threadIdx.x;
    int lane = tid & 31, warp = tid >> 5;
    __shared__ float z[16];
    __shared__ float wsm[Tz];
    if (warp < Tz) {
        const float* cp = C_past + ((size_t)b * Tz + warp) * Dz;
        const float* cb = g_ci + b * Dz;
        float sum = 0.f;
        #pragma unroll 4
        for (int d = lane; d < Dz; d += 32) sum += cb[d] * cp[d] * Wwcc[d];
        #pragma unroll
        for (int o = 16; o; o >>= 1) sum += __shfl_xor_sync(0xffffffffu, sum, o);
        if (lane == 0) z[warp] = sum;
    }
    __syncthreads();
    if (tid == 0) {
        float mx = -1e30f;
        for (int t = 0; t < Tz; t++) mx = fmaxf(mx, z[t]);
        float s = 0.f;
        for (int t = 0; t < Tz; t++) { float e = expf(z[t] - mx); wsm[t] = e; s += e; }
        float inv = 1.f / s;
        for (int t = 0; t < Tz; t++) wsm[t] *= inv;
    }
    __syncthreads();
    float acc = 0.f;
    #pragma unroll
    for (int t = 0; t < Tz; t++)
        acc += wsm[t] * M_past[((size_t)b * Tz + t) * Dz + tid];
    g_mi_sa[b * Dz + tid] = acc;
}

// ---------------- gate + final ----------------
__global__ void __launch_bounds__(512) final_kernel(const float* __restrict__ mi_1,
                                                    const float* __restrict__ Wwci,
                                                    const float* __restrict__ bwci,
                                                    float* __restrict__ out)
{
    int b = blockIdx.x, tid = threadIdx.x;
    __shared__ float red[16];
    __shared__ float gsh;
    float civ = g_ci[b * Dz + tid];
    float sum = civ * Wwci[tid];
    #pragma unroll
    for (int o = 16; o; o >>= 1) sum += __shfl_xor_sync(0xffffffffu, sum, o);
    if ((tid & 31) == 0) red[tid >> 5] = sum;
    __syncthreads();
    if (tid < 32) {
        float v = (tid < 16) ? red[tid] : 0.f;
        #pragma unroll
        for (int o = 8; o; o >>= 1) v += __shfl_xor_sync(0xffffffffu, v, o);
        if (tid == 0) gsh = 1.f / (1.f + expf(-(v + bwci[0])));
    }
    __syncthreads();
    float g = gsh;
    float mi = g * mi_1[b * Dz + tid] + (1.f - g) * g_mi_prime[b * Dz + tid];
    out[b * Dz + tid] = civ;
    out[(size_t)Bz * Dz + b * Dz + tid] = mi;
}

// ---------------- launch ----------------
extern "C" void kernel_launch(void* const* d_in, const int* in_sizes, int n_in,
                              void* d_out, int out_size)
{
    const float* ci_1   = (const float*)d_in[0];
    const float* mi_1   = (const float*)d_in[1];
    const float* q      = (const float*)d_in[2];
    const float* cws    = (const float*)d_in[3];
    const float* Kt     = (const float*)d_in[4];
    const float* C_past = (const float*)d_in[5];
    const float* M_past = (const float*)d_in[6];
    const float* W_cq   = (const float*)d_in[7];
    const float* b_cq   = (const float*)d_in[8];
    const float* W_cqi  = (const float*)d_in[9];
    const float* b_cqi  = (const float*)d_in[10];
    const float* W_cai  = (const float*)d_in[11];
    const float* W_rm   = (const float*)d_in[13];
    const float* b_rm   = (const float*)d_in[14];
    const float* W_rk   = (const float*)d_in[15];
    const float* b_rk   = (const float*)d_in[16];
    const float* W_rik  = (const float*)d_in[17];
    const float* b_rik  = (const float*)d_in[18];
    const float* W_rci  = (const float*)d_in[19];
    const float* b_rci  = (const float*)d_in[20];
    const float* W_wrm  = (const float*)d_in[21];
    const float* b_wrm  = (const float*)d_in[22];
    const float* W_wcc  = (const float*)d_in[23];
    const float* W_wsa  = (const float*)d_in[25];
    const float* b_wsa  = (const float*)d_in[26];
    const float* W_winfo= (const float*)d_in[27];
    const float* b_winfo= (const float*)d_in[28];
    const float* W_wci  = (const float*)d_in[29];
    const float* b_wci  = (const float*)d_in[30];
    float* out = (float*)d_out;

    float *qi, *cqi, *ci, *rm, *rai, *ri, *mi_info, *mi_sa, *mi_prime;
    __nv_bfloat16 *K_bf, *rk_bf, *ip_bf, *Wt_rk, *Wt_rik, *Wt_rci;
    cudaGetSymbolAddress((void**)&qi, g_qi);
    cudaGetSymbolAddress((void**)&cqi, g_cqi);
    cudaGetSymbolAddress((void**)&ci, g_ci);
    cudaGetSymbolAddress((void**)&rm, g_rm);
    cudaGetSymbolAddress((void**)&rai, g_rai);
    cudaGetSymbolAddress((void**)&ri, g_ri);
    cudaGetSymbolAddress((void**)&mi_info, g_mi_info);
    cudaGetSymbolAddress((void**)&mi_sa, g_mi_sa);
    cudaGetSymbolAddress((void**)&mi_prime, g_mi_prime);
    cudaGetSymbolAddress((void**)&K_bf, g_K_bf);
    cudaGetSymbolAddress((void**)&rk_bf, g_rk_bf);
    cudaGetSymbolAddress((void**)&ip_bf, g_ip_bf);
    cudaGetSymbolAddress((void**)&Wt_rk, g_Wt_rk);
    cudaGetSymbolAddress((void**)&Wt_rik, g_Wt_rik);
    cudaGetSymbolAddress((void**)&Wt_rci, g_Wt_rci);

    cudaFuncSetAttribute(hgemm_kernel,
                         cudaFuncAttributeMaxDynamicSharedMemorySize, HG_SMEM);

    dim3 gs(Dz / 128, Bz / 128);     // small GEMMs
    dim3 gh(Mbig / 128, Dz / 128);   // big GEMMs: (392, 4)

    // ---- precompute: bf16 conversions ----
    f2bf_kernel<<<(Mbig * Dz) / 1024, 256>>>(Kt, K_bf);
    transpose_w_kernel<<<dim3(Dz/32, Dz/32), 256>>>(W_rk, Wt_rk, Dz, Dz);
    transpose_w_kernel<<<dim3(2*Dz/32, Dz/32), 256>>>(W_rik, Wt_rik, 2*Dz, Dz);
    transpose_w_kernel<<<dim3(Dz/32, Dz/32), 256>>>(W_rci, Wt_rci, Dz, Dz);

    // ---- control (fp32) ----
    sgemm_kernel<<<gs, 256>>>(q, W_cq, b_cq, qi, Bz, Dz, Dz, nullptr, 1, 0);
    sgemm_kernel<<<gs, 256>>>(ci_1, W_cqi, b_cqi, cqi, Bz, Dz, Dz, nullptr, 1, 0);
    sgemm_kernel<<<gs, 256>>>(qi, W_cqi + Dz * Dz, nullptr, cqi, Bz, Dz, Dz, nullptr, 1, 1);
    cai_kernel<<<(Bz * Sz) / 8, 256>>>(cws, W_cai);
    ci_kernel<<<Bz, 128>>>(cws);

    // ---- read (bf16 HMMA big GEMMs, scalings folded into epilogues) ----
    sgemm_kernel<<<gs, 256>>>(mi_1, W_rm, b_rm, rm, Bz, Dz, Dz, nullptr, 1, 0);
    // rk_bf = rm ⊙ (K @ W_rk + b_rk)
    hgemm_kernel<<<gh, 256, HG_SMEM>>>(K_bf, nullptr, Wt_rk, b_rk, rm, rk_bf, 1, Dz, Dz);
    // ip_bf = ci ⊙ (concat(rk_bf, K) @ W_rik + b_rik)
    hgemm_kernel<<<gh, 256, HG_SMEM>>>(rk_bf, K_bf, Wt_rik, b_rik, ci, ip_bf, 1, Dz, 2*Dz);
    // rai = ip_bf @ W_rci + b_rci  (fp32 out)
    hgemm_kernel<<<gh, 256, HG_SMEM>>>(ip_bf, nullptr, Wt_rci, b_rci, nullptr, rai, 0, Dz, Dz);
    rsoft_kernel<<<Bz, Dz>>>(Kt);

    // ---- write (fp32) ----
    sgemm_kernel<<<gs, 256>>>(ri, W_wrm, b_wrm, mi_info, Bz, Dz, Dz, nullptr, 1, 0);
    sgemm_kernel<<<gs, 256>>>(mi_1, W_wrm + Dz * Dz, nullptr, mi_info, Bz, Dz, Dz, nullptr, 1, 1);
    sa_kernel<<<Bz, 512>>>(C_past, M_past, W_wcc);
    sgemm_kernel<<<gs, 256>>>(mi_sa, W_wsa, b_wsa, mi_prime, Bz, Dz, Dz, nullptr, 1, 0);
    sgemm_kernel<<<gs, 256>>>(mi_info, W_winfo, b_winfo, mi_prime, Bz, Dz, Dz, nullptr, 1, 1);
    final_kernel<<<Bz, 512>>>(mi_1, W_wci, b_wci, out);
}

// round 9
// speedup vs baseline: 2.6551x; 1.0363x over previous
#include <cuda_runtime.h>
#include <cuda_bf16.h>
#include <stdint.h>
#include <math.h>

#define Bz 256
#define Sz 128
#define Hz 14
#define Wz 14
#define Tz 12
#define Dz 512
#define HWz (Hz*Wz)
#define Mbig (Bz*HWz)   // 50176

// ---------------- scratch (device globals; no allocation) ----------------
__device__ float g_qi[Bz*Dz];
__device__ float g_cqi[Bz*Dz];
__device__ float g_cai[Bz*Sz];
__device__ float g_ci[Bz*Dz];
__device__ float g_rm[Bz*Dz];
__device__ float g_ri[Bz*Dz];
__device__ float g_mi_info[Bz*Dz];
__device__ float g_mi_sa[Bz*Dz];
__device__ float g_mi_prime[Bz*Dz];
__device__ float g_rai[(size_t)Mbig*Dz];
__device__ __nv_bfloat16 g_K_bf[(size_t)Mbig*Dz];
__device__ __nv_bfloat16 g_rk_bf[(size_t)Mbig*Dz];   // rm ⊙ (K@W_rk + b_rk)
__device__ __nv_bfloat16 g_ip_bf[(size_t)Mbig*Dz];   // ci ⊙ (concat@W_rik + b_rik)
__device__ __nv_bfloat16 g_Wt_rk[Dz*Dz];
__device__ __nv_bfloat16 g_Wt_rik[2*Dz*Dz];
__device__ __nv_bfloat16 g_Wt_rci[Dz*Dz];

// ================= helpers =================
__device__ __forceinline__ uint32_t smem_u32(const void* p) {
    uint32_t a;
    asm("{ .reg .u64 t; cvta.to.shared.u64 t, %1; cvt.u32.u64 %0, t; }" : "=r"(a) : "l"(p));
    return a;
}
__device__ __forceinline__ void cp16(uint32_t dst, const void* src) {
    asm volatile("cp.async.cg.shared.global [%0], [%1], 16;" :: "r"(dst), "l"(src) : "memory");
}
__device__ __forceinline__ void mma_bf16(float* c, uint32_t a0, uint32_t a1,
                                         uint32_t a2, uint32_t a3,
                                         uint32_t b0, uint32_t b1) {
    asm volatile("mma.sync.aligned.m16n8k16.row.col.f32.bf16.bf16.f32 "
        "{%0,%1,%2,%3}, {%4,%5,%6,%7}, {%8,%9}, {%0,%1,%2,%3};"
        : "+f"(c[0]), "+f"(c[1]), "+f"(c[2]), "+f"(c[3])
        : "r"(a0), "r"(a1), "r"(a2), "r"(a3), "r"(b0), "r"(b1));
}
__device__ __forceinline__ void ldm4(uint32_t& r0, uint32_t& r1, uint32_t& r2,
                                     uint32_t& r3, uint32_t addr) {
    asm volatile("ldmatrix.sync.aligned.m8n8.x4.shared.b16 {%0,%1,%2,%3}, [%4];"
        : "=r"(r0), "=r"(r1), "=r"(r2), "=r"(r3) : "r"(addr));
}

#define TSTRIDE 80                  // bytes per smem tile row (32 bf16 + 8 pad)
#define TILE_BYTES (128*TSTRIDE)    // 10240
#define HG_SMEM (6*TILE_BYTES)      // 61440: A x3 stages, B x3 stages

// ================= bf16 HMMA GEMM (3-stage cp.async, ldmatrix) =================
// C[M,512] = Acat[M,Ktot] @ W[Ktot,512] + bias, then optional ⊙ scale[row/196, col]
// Acat[m,k] = (k<K1) ? A1[m,k] : A2[m,k-K1]   (A2 row stride 512, bf16)
// Bt = W^T bf16, [512][Ktot] row-major.
__global__ void __launch_bounds__(256, 2) hgemm_kernel(
    const __nv_bfloat16* __restrict__ A1,
    const __nv_bfloat16* __restrict__ A2,
    const __nv_bfloat16* __restrict__ Bt,
    const float* __restrict__ bias,
    const float* __restrict__ scale,
    void* __restrict__ Cout, int c_is_bf16,
    int K1, int Ktot)
{
    extern __shared__ char sm[];
    const uint32_t sa_base = smem_u32(sm);
    const uint32_t sb_base = sa_base + 3 * TILE_BYTES;

    const int tid  = threadIdx.x;
    const int m0   = blockIdx.x * 128;
    const int n0   = blockIdx.y * 128;
    const int warp = tid >> 5;
    const int lane = tid & 31;
    const int wm = warp >> 2;        // 0..1 (64 rows)
    const int wn = warp & 3;         // 0..3 (32 cols)
    const int g  = lane >> 2;
    const int t  = lane & 3;

    float acc[4][4][4];
    #pragma unroll
    for (int i = 0; i < 4; i++)
        #pragma unroll
        for (int j = 0; j < 4; j++)
            #pragma unroll
            for (int k = 0; k < 4; k++) acc[i][j][k] = 0.f;

    const int nch = Ktot >> 5;

    auto load_tile = [&](int c) {
        const int kt = c << 5;
        const int s = c % 3;
        uint32_t ab = sa_base + s * TILE_BYTES;
        uint32_t bb = sb_base + s * TILE_BYTES;
        #pragma unroll
        for (int i = 0; i < 2; i++) {
            int chunk = tid + (i << 8);
            int row = chunk >> 2, cc = chunk & 3;
            int kg = kt + (cc << 3);
            const __nv_bfloat16* sa = (kg < K1)
                ? (A1 + (size_t)(m0 + row) * K1 + kg)
                : (A2 + (size_t)(m0 + row) * Dz + (kg - K1));
            cp16(ab + row * TSTRIDE + cc * 16, sa);
            cp16(bb + row * TSTRIDE + cc * 16,
                 Bt + (size_t)(n0 + row) * Ktot + kt + (cc << 3));
        }
        asm volatile("cp.async.commit_group;" ::: "memory");
    };

    load_tile(0);
    load_tile(1);
    for (int c = 0; c < nch; c++) {
        if (c + 1 < nch) asm volatile("cp.async.wait_group 1;" ::: "memory");
        else             asm volatile("cp.async.wait_group 0;" ::: "memory");
        __syncthreads();
        if (c + 2 < nch) load_tile(c + 2);

        const int s = c % 3;
        const uint32_t ab = sa_base + s * TILE_BYTES;
        const uint32_t bb = sb_base + s * TILE_BYTES;
        #pragma unroll
        for (int ks = 0; ks < 2; ks++) {
            uint32_t bfr[4][2];
            #pragma unroll
            for (int j = 0; j < 2; j++) {
                uint32_t addr = bb + (uint32_t)((wn * 32 + j * 16 + ((lane >> 4) & 1) * 8
                                + (lane & 7)) * TSTRIDE + ks * 32 + ((lane >> 3) & 1) * 16);
                ldm4(bfr[2*j][0], bfr[2*j][1], bfr[2*j+1][0], bfr[2*j+1][1], addr);
            }
            #pragma unroll
            for (int am = 0; am < 4; am++) {
                uint32_t addr = ab + (uint32_t)((wm * 64 + am * 16 + (lane & 15)) * TSTRIDE
                                + ks * 32 + ((lane >> 4) & 1) * 16);
                uint32_t a0, a1, a2, a3;
                ldm4(a0, a1, a2, a3, addr);
                #pragma unroll
                for (int an = 0; an < 4; an++)
                    mma_bf16(acc[am][an], a0, a1, a2, a3, bfr[an][0], bfr[an][1]);
            }
        }
    }

    // ---- epilogue: c0:(g,2t) c1:(g,2t+1) c2:(g+8,2t) c3:(g+8,2t+1) ----
    #pragma unroll
    for (int am = 0; am < 4; am++) {
        int r0 = m0 + wm * 64 + am * 16 + g;
        int r1 = r0 + 8;
        #pragma unroll
        for (int an = 0; an < 4; an++) {
            int col = n0 + wn * 32 + an * 8 + t * 2;
            float b0 = bias[col], b1 = bias[col + 1];
            float v00 = acc[am][an][0] + b0, v01 = acc[am][an][1] + b1;
            float v10 = acc[am][an][2] + b0, v11 = acc[am][an][3] + b1;
            if (scale) {
                const float* s0 = scale + (size_t)(r0 / HWz) * Dz + col;
                const float* s1 = scale + (size_t)(r1 / HWz) * Dz + col;
                v00 *= s0[0]; v01 *= s0[1];
                v10 *= s1[0]; v11 *= s1[1];
            }
            if (c_is_bf16) {
                union { __nv_bfloat162 h; uint32_t u; } p0, p1;
                p0.h = __floats2bfloat162_rn(v00, v01);
                p1.h = __floats2bfloat162_rn(v10, v11);
                *(uint32_t*)((__nv_bfloat16*)Cout + (size_t)r0 * Dz + col) = p0.u;
                *(uint32_t*)((__nv_bfloat16*)Cout + (size_t)r1 * Dz + col) = p1.u;
            } else {
                *(float2*)((float*)Cout + (size_t)r0 * Dz + col) = make_float2(v00, v01);
                *(float2*)((float*)Cout + (size_t)r1 * Dz + col) = make_float2(v10, v11);
            }
        }
    }
}

// ---------------- fp32 -> bf16 bulk convert ----------------
__global__ void __launch_bounds__(256) f2bf_kernel(const float* __restrict__ in,
                                                   __nv_bfloat16* __restrict__ out)
{
    size_t i = ((size_t)blockIdx.x * 256 + threadIdx.x) * 4;
    float4 v = *(const float4*)(in + i);
    union { __nv_bfloat162 h; uint32_t u; } p0, p1;
    p0.h = __floats2bfloat162_rn(v.x, v.y);
    p1.h = __floats2bfloat162_rn(v.z, v.w);
    *(uint2*)(out + i) = make_uint2(p0.u, p1.u);
}

// ---------------- weight transpose: Wt[n][k] = (bf16) W[k][n] ----------------
__global__ void __launch_bounds__(256) transpose_w_kernel(
    const float* __restrict__ W, __nv_bfloat16* __restrict__ Wt, int K, int N)
{
    __shared__ float t[32][33];
    int k0 = blockIdx.x * 32, n0 = blockIdx.y * 32;
    int x = threadIdx.x & 31, y = threadIdx.x >> 5;
    #pragma unroll
    for (int j = 0; j < 32; j += 8)
        t[y + j][x] = W[(size_t)(k0 + y + j) * N + n0 + x];
    __syncthreads();
    #pragma unroll
    for (int j = 0; j < 32; j += 8)
        Wt[(size_t)(n0 + y + j) * K + k0 + x] = __float2bfloat16(t[x][y + j]);
}

// ---------------- fp32 SGEMM with concat-A and stacked-B support ----------------
// C[M,N] = concat(A1,A2)[M,Ktot] @ stack(B1,B2)[Ktot,N] + bias (+bias2)
// A1 rows of width K1 (stride K1), A2 stride 512. B2 used for rows >= KB1.
__global__ void __launch_bounds__(256) sgemm_kernel(
    const float* __restrict__ A1, const float* __restrict__ A2,
    const float* __restrict__ B1, const float* __restrict__ B2,
    const float* __restrict__ bias, const float* __restrict__ bias2,
    float* __restrict__ C,
    int M, int N, int K1, int KB1, int Ktot)
{
    __shared__ float As[8][128];
    __shared__ float Bs[8][128];
    const int tid = threadIdx.x;
    const int m0 = blockIdx.y * 128;
    const int n0 = blockIdx.x * 128;
    const int tx = tid & 15;
    const int ty = tid >> 4;
    const int aRow = tid >> 1;
    const int aCol = (tid & 1) << 2;
    const int bRow = tid >> 5;
    const int bCol = (tid & 31) << 2;

    float acc[8][8];
    #pragma unroll
    for (int i = 0; i < 8; i++)
        #pragma unroll
        for (int j = 0; j < 8; j++) acc[i][j] = 0.f;

    for (int kt = 0; kt < Ktot; kt += 8) {
        int kg = kt + aCol;
        const float* ap = (kg < K1)
            ? (A1 + (size_t)(m0 + aRow) * K1 + kg)
            : (A2 + (size_t)(m0 + aRow) * Dz + (kg - K1));
        float4 a = *(const float4*)ap;
        As[aCol + 0][aRow] = a.x;
        As[aCol + 1][aRow] = a.y;
        As[aCol + 2][aRow] = a.z;
        As[aCol + 3][aRow] = a.w;
        int kr = kt + bRow;
        const float* bp = (kr < KB1)
            ? (B1 + (size_t)kr * N + n0 + bCol)
            : (B2 + (size_t)(kr - KB1) * N + n0 + bCol);
        *(float4*)&Bs[bRow][bCol] = *(const float4*)bp;
        __syncthreads();
        #pragma unroll
        for (int k = 0; k < 8; k++) {
            float ar[8], br[8];
            #pragma unroll
            for (int i = 0; i < 8; i++) ar[i] = As[k][ty * 8 + i];
            #pragma unroll
            for (int j = 0; j < 8; j++) br[j] = Bs[k][tx * 8 + j];
            #pragma unroll
            for (int i = 0; i < 8; i++)
                #pragma unroll
                for (int j = 0; j < 8; j++)
                    acc[i][j] = fmaf(ar[i], br[j], acc[i][j]);
        }
        __syncthreads();
    }
    #pragma unroll
    for (int i = 0; i < 8; i++) {
        int row = m0 + ty * 8 + i;
        float* crow = C + (size_t)row * N + n0 + tx * 8;
        #pragma unroll
        for (int j = 0; j < 8; j++) {
            float v = acc[i][j] + bias[n0 + tx * 8 + j];
            if (bias2) v += bias2[n0 + tx * 8 + j];
            crow[j] = v;
        }
    }
}

// ---------------- cai[b,s] = sum_d cqi[b,d]*cws[b,s,d]*W_cai[d] ----------------
__global__ void __launch_bounds__(256) cai_kernel(const float* __restrict__ cws,
                                                  const float* __restrict__ Wcai)
{
    int warp = (blockIdx.x * blockDim.x + threadIdx.x) >> 5;
    int lane = threadIdx.x & 31;
    if (warp >= Bz * Sz) return;
    int b = warp / Sz;
    const float* cq = g_cqi + b * Dz;
    const float* cw = cws + (size_t)warp * Dz;
    float sum = 0.f;
    #pragma unroll 4
    for (int d = lane; d < Dz; d += 32)
        sum += cq[d] * cw[d] * Wcai[d];
    #pragma unroll
    for (int o = 16; o; o >>= 1) sum += __shfl_xor_sync(0xffffffffu, sum, o);
    if (lane == 0) g_cai[warp] = sum;
}

// ---------------- softmax over S + ci reduction ----------------
__global__ void __launch_bounds__(128) ci_kernel(const float* __restrict__ cws)
{
    int b = blockIdx.x, tid = threadIdx.x;
    __shared__ float wsm[Sz];
    __shared__ float red[4];
    float x = g_cai[b * Sz + tid];
    float m = x;
    #pragma unroll
    for (int o = 16; o; o >>= 1) m = fmaxf(m, __shfl_xor_sync(0xffffffffu, m, o));
    if ((tid & 31) == 0) red[tid >> 5] = m;
    __syncthreads();
    float bm = fmaxf(fmaxf(red[0], red[1]), fmaxf(red[2], red[3]));
    __syncthreads();
    float e = expf(x - bm);
    float s = e;
    #pragma unroll
    for (int o = 16; o; o >>= 1) s += __shfl_xor_sync(0xffffffffu, s, o);
    if ((tid & 31) == 0) red[tid >> 5] = s;
    __syncthreads();
    float bs = red[0] + red[1] + red[2] + red[3];
    wsm[tid] = e / bs;
    __syncthreads();
    for (int d = tid; d < Dz; d += 128) {
        float acc = 0.f;
        #pragma unroll 8
        for (int s2 = 0; s2 < Sz; s2++)
            acc += wsm[s2] * cws[((size_t)b * Sz + s2) * Dz + d];
        g_ci[b * Dz + d] = acc;
    }
}

// ---------------- double softmax + ri, smem-staged (one global pass) ----------------
#define RS_SMEM (HWz*128*4)   // 196*128 fp32 = 100352 B
__global__ void __launch_bounds__(128) rsoft_kernel(const float* __restrict__ rai,
                                                    const float* __restrict__ Kt)
{
    extern __shared__ float sd[];   // [196][128]
    const int b = blockIdx.x;
    const int d0 = blockIdx.y * 128;
    const int tid = threadIdx.x;
    const float* src = rai + (size_t)b * HWz * Dz + d0;

    // stage the whole (batch, d-chunk) slab
    for (int i = tid; i < HWz * 32; i += 128) {
        int pos = i >> 5, c4 = (i & 31) << 2;
        *(float4*)(sd + pos * 128 + c4) = *(const float4*)(src + (size_t)pos * Dz + c4);
    }
    __syncthreads();

    // pass 1: softmax over H for each w (in smem)
    for (int w = 0; w < Wz; w++) {
        float v[Hz];
        float mx = -1e30f;
        #pragma unroll
        for (int h = 0; h < Hz; h++) { v[h] = sd[(h * Wz + w) * 128 + tid]; mx = fmaxf(mx, v[h]); }
        float s = 0.f;
        #pragma unroll
        for (int h = 0; h < Hz; h++) { v[h] = expf(v[h] - mx); s += v[h]; }
        float inv = 1.f / s;
        #pragma unroll
        for (int h = 0; h < Hz; h++) sd[(h * Wz + w) * 128 + tid] = v[h] * inv;
    }
    __syncthreads();

    // pass 2: softmax over W of probs, fused with ri reduction
    const float* kp = Kt + (size_t)b * HWz * Dz + d0 + tid;
    float acc = 0.f;
    for (int h = 0; h < Hz; h++) {
        float v[Wz];
        float mx = -1e30f;
        #pragma unroll
        for (int w = 0; w < Wz; w++) { v[w] = sd[(h * Wz + w) * 128 + tid]; mx = fmaxf(mx, v[w]); }
        float s = 0.f;
        #pragma unroll
        for (int w = 0; w < Wz; w++) { v[w] = expf(v[w] - mx); s += v[w]; }
        float inv = 1.f / s;
        #pragma unroll
        for (int w = 0; w < Wz; w++) acc += v[w] * inv * kp[(size_t)(h * Wz + w) * Dz];
    }
    g_ri[b * Dz + d0 + tid] = acc;
}

// ---------------- write attention ----------------
__global__ void __launch_bounds__(512) sa_kernel(const float* __restrict__ C_past,
                                                 const float* __restrict__ M_past,
                                                 const float* __restrict__ Wwcc)
{
    int b = blockIdx.x, tid = threadIdx.x;
    int lane = tid & 31, warp = tid >> 5;
    __shared__ float z[16];
    __shared__ float wsm[Tz];
    if (warp < Tz) {
        const float* cp = C_past + ((size_t)b * Tz + warp) * Dz;
        const float* cb = g_ci + b * Dz;
        float sum = 0.f;
        #pragma unroll 4
        for (int d = lane; d < Dz; d += 32) sum += cb[d] * cp[d] * Wwcc[d];
        #pragma unroll
        for (int o = 16; o; o >>= 1) sum += __shfl_xor_sync(0xffffffffu, sum, o);
        if (lane == 0) z[warp] = sum;
    }
    __syncthreads();
    if (tid == 0) {
        float mx = -1e30f;
        for (int t = 0; t < Tz; t++) mx = fmaxf(mx, z[t]);
        float s = 0.f;
        for (int t = 0; t < Tz; t++) { float e = expf(z[t] - mx); wsm[t] = e; s += e; }
        float inv = 1.f / s;
        for (int t = 0; t < Tz; t++) wsm[t] *= inv;
    }
    __syncthreads();
    float acc = 0.f;
    #pragma unroll
    for (int t = 0; t < Tz; t++)
        acc += wsm[t] * M_past[((size_t)b * Tz + t) * Dz + tid];
    g_mi_sa[b * Dz + tid] = acc;
}

// ---------------- gate + final ----------------
__global__ void __launch_bounds__(512) final_kernel(const float* __restrict__ mi_1,
                                                    const float* __restrict__ Wwci,
                                                    const float* __restrict__ bwci,
                                                    float* __restrict__ out)
{
    int b = blockIdx.x, tid = threadIdx.x;
    __shared__ float red[16];
    __shared__ float gsh;
    float civ = g_ci[b * Dz + tid];
    float sum = civ * Wwci[tid];
    #pragma unroll
    for (int o = 16; o; o >>= 1) sum += __shfl_xor_sync(0xffffffffu, sum, o);
    if ((tid & 31) == 0) red[tid >> 5] = sum;
    __syncthreads();
    if (tid < 32) {
        float v = (tid < 16) ? red[tid] : 0.f;
        #pragma unroll
        for (int o = 8; o; o >>= 1) v += __shfl_xor_sync(0xffffffffu, v, o);
        if (tid == 0) gsh = 1.f / (1.f + expf(-(v + bwci[0])));
    }
    __syncthreads();
    float g = gsh;
    float mi = g * mi_1[b * Dz + tid] + (1.f - g) * g_mi_prime[b * Dz + tid];
    out[b * Dz + tid] = civ;
    out[(size_t)Bz * Dz + b * Dz + tid] = mi;
}

// ---------------- launch ----------------
extern "C" void kernel_launch(void* const* d_in, const int* in_sizes, int n_in,
                              void* d_out, int out_size)
{
    const float* ci_1   = (const float*)d_in[0];
    const float* mi_1   = (const float*)d_in[1];
    const float* q      = (const float*)d_in[2];
    const float* cws    = (const float*)d_in[3];
    const float* Kt     = (const float*)d_in[4];
    const float* C_past = (const float*)d_in[5];
    const float* M_past = (const float*)d_in[6];
    const float* W_cq   = (const float*)d_in[7];
    const float* b_cq   = (const float*)d_in[8];
    const float* W_cqi  = (const float*)d_in[9];
    const float* b_cqi  = (const float*)d_in[10];
    const float* W_cai  = (const float*)d_in[11];
    const float* W_rm   = (const float*)d_in[13];
    const float* b_rm   = (const float*)d_in[14];
    const float* W_rk   = (const float*)d_in[15];
    const float* b_rk   = (const float*)d_in[16];
    const float* W_rik  = (const float*)d_in[17];
    const float* b_rik  = (const float*)d_in[18];
    const float* W_rci  = (const float*)d_in[19];
    const float* b_rci  = (const float*)d_in[20];
    const float* W_wrm  = (const float*)d_in[21];
    const float* b_wrm  = (const float*)d_in[22];
    const float* W_wcc  = (const float*)d_in[23];
    const float* W_wsa  = (const float*)d_in[25];
    const float* b_wsa  = (const float*)d_in[26];
    const float* W_winfo= (const float*)d_in[27];
    const float* b_winfo= (const float*)d_in[28];
    const float* W_wci  = (const float*)d_in[29];
    const float* b_wci  = (const float*)d_in[30];
    float* out = (float*)d_out;

    float *qi, *cqi, *ci, *rm, *rai, *ri, *mi_info, *mi_sa, *mi_prime;
    __nv_bfloat16 *K_bf, *rk_bf, *ip_bf, *Wt_rk, *Wt_rik, *Wt_rci;
    cudaGetSymbolAddress((void**)&qi, g_qi);
    cudaGetSymbolAddress((void**)&cqi, g_cqi);
    cudaGetSymbolAddress((void**)&ci, g_ci);
    cudaGetSymbolAddress((void**)&rm, g_rm);
    cudaGetSymbolAddress((void**)&rai, g_rai);
    cudaGetSymbolAddress((void**)&ri, g_ri);
    cudaGetSymbolAddress((void**)&mi_info, g_mi_info);
    cudaGetSymbolAddress((void**)&mi_sa, g_mi_sa);
    cudaGetSymbolAddress((void**)&mi_prime, g_mi_prime);
    cudaGetSymbolAddress((void**)&K_bf, g_K_bf);
    cudaGetSymbolAddress((void**)&rk_bf, g_rk_bf);
    cudaGetSymbolAddress((void**)&ip_bf, g_ip_bf);
    cudaGetSymbolAddress((void**)&Wt_rk, g_Wt_rk);
    cudaGetSymbolAddress((void**)&Wt_rik, g_Wt_rik);
    cudaGetSymbolAddress((void**)&Wt_rci, g_Wt_rci);

    cudaFuncSetAttribute(hgemm_kernel,
                         cudaFuncAttributeMaxDynamicSharedMemorySize, HG_SMEM);
    cudaFuncSetAttribute(rsoft_kernel,
                         cudaFuncAttributeMaxDynamicSharedMemorySize, RS_SMEM);

    dim3 gs(Dz / 128, Bz / 128);     // small GEMMs: (4, 2)
    dim3 gh(Mbig / 128, Dz / 128);   // big GEMMs: (392, 4)

    // ---- precompute: bf16 conversions ----
    f2bf_kernel<<<(Mbig * Dz) / 1024, 256>>>(Kt, K_bf);
    transpose_w_kernel<<<dim3(Dz/32, Dz/32), 256>>>(W_rk, Wt_rk, Dz, Dz);
    transpose_w_kernel<<<dim3(2*Dz/32, Dz/32), 256>>>(W_rik, Wt_rik, 2*Dz, Dz);
    transpose_w_kernel<<<dim3(Dz/32, Dz/32), 256>>>(W_rci, Wt_rci, Dz, Dz);

    // ---- control (fp32) ----
    sgemm_kernel<<<gs, 256>>>(q, nullptr, W_cq, nullptr, b_cq, nullptr, qi,
                              Bz, Dz, Dz, 2*Dz, Dz);
    sgemm_kernel<<<gs, 256>>>(ci_1, qi, W_cqi, nullptr, b_cqi, nullptr, cqi,
                              Bz, Dz, Dz, 2*Dz, 2*Dz);
    cai_kernel<<<(Bz * Sz) / 8, 256>>>(cws, W_cai);
    ci_kernel<<<Bz, 128>>>(cws);

    // ---- read (bf16 HMMA big GEMMs, scalings folded into epilogues) ----
    sgemm_kernel<<<gs, 256>>>(mi_1, nullptr, W_rm, nullptr, b_rm, nullptr, rm,
                              Bz, Dz, Dz, 2*Dz, Dz);
    // rk_bf = rm ⊙ (K @ W_rk + b_rk)
    hgemm_kernel<<<gh, 256, HG_SMEM>>>(K_bf, nullptr, Wt_rk, b_rk, rm, rk_bf, 1, Dz, Dz);
    // ip_bf = ci ⊙ (concat(rk_bf, K) @ W_rik + b_rik)
    hgemm_kernel<<<gh, 256, HG_SMEM>>>(rk_bf, K_bf, Wt_rik, b_rik, ci, ip_bf, 1, Dz, 2*Dz);
    // rai = ip_bf @ W_rci + b_rci  (fp32 out)
    hgemm_kernel<<<gh, 256, HG_SMEM>>>(ip_bf, nullptr, Wt_rci, b_rci, nullptr, rai, 0, Dz, Dz);
    rsoft_kernel<<<dim3(Bz, Dz/128), 128, RS_SMEM>>>(rai, Kt);

    // ---- write (fp32) ----
    sgemm_kernel<<<gs, 256>>>(ri, mi_1, W_wrm, nullptr, b_wrm, nullptr, mi_info,
                              Bz, Dz, Dz, 2*Dz, 2*Dz);
    sa_kernel<<<Bz, 512>>>(C_past, M_past, W_wcc);
    // mi_prime = concat(mi_sa, mi_info) @ stack(W_wsa, W_winfo) + b_wsa + b_winfo
    sgemm_kernel<<<gs, 256>>>(mi_sa, mi_info, W_wsa, W_winfo, b_wsa, b_winfo, mi_prime,
                              Bz, Dz, Dz, Dz, 2*Dz);
    final_kernel<<<Bz, 512>>>(mi_1, W_wci, b_wci, out);
}

// round 10
// speedup vs baseline: 2.6835x; 1.0107x over previous
#include <cuda_runtime.h>
#include <cuda_bf16.h>
#include <stdint.h>
#include <math.h>

#define Bz 256
#define Sz 128
#define Hz 14
#define Wz 14
#define Tz 12
#define Dz 512
#define HWz (Hz*Wz)
#define Mbig (Bz*HWz)   // 50176

// ---------------- scratch (device globals; no allocation) ----------------
__device__ float g_qi[Bz*Dz];
__device__ float g_cqi[Bz*Dz];
__device__ float g_cai[Bz*Sz];
__device__ float g_ci[Bz*Dz];
__device__ float g_rm[Bz*Dz];
__device__ float g_ri[Bz*Dz];
__device__ float g_mi_info[Bz*Dz];
__device__ float g_mi_sa[Bz*Dz];
__device__ float g_mi_prime[Bz*Dz];
__device__ float g_rai[(size_t)Mbig*Dz];
__device__ __nv_bfloat16 g_K_bf[(size_t)Mbig*Dz];
__device__ __nv_bfloat16 g_rk_bf[(size_t)Mbig*Dz];   // rm ⊙ (K@W_rk + b_rk)
__device__ __nv_bfloat16 g_ip_bf[(size_t)Mbig*Dz];   // ci ⊙ (concat@W_rik + b_rik)
__device__ __nv_bfloat16 g_Wt_rk[Dz*Dz];
__device__ __nv_bfloat16 g_Wt_rik[2*Dz*Dz];
__device__ __nv_bfloat16 g_Wt_rci[Dz*Dz];

// ================= helpers =================
__device__ __forceinline__ uint32_t smem_u32(const void* p) {
    uint32_t a;
    asm("{ .reg .u64 t; cvta.to.shared.u64 t, %1; cvt.u32.u64 %0, t; }" : "=r"(a) : "l"(p));
    return a;
}
__device__ __forceinline__ void cp16(uint32_t dst, const void* src) {
    asm volatile("cp.async.cg.shared.global [%0], [%1], 16;" :: "r"(dst), "l"(src) : "memory");
}
__device__ __forceinline__ void mma_bf16(float* c, uint32_t a0, uint32_t a1,
                                         uint32_t a2, uint32_t a3,
                                         uint32_t b0, uint32_t b1) {
    asm volatile("mma.sync.aligned.m16n8k16.row.col.f32.bf16.bf16.f32 "
        "{%0,%1,%2,%3}, {%4,%5,%6,%7}, {%8,%9}, {%0,%1,%2,%3};"
        : "+f"(c[0]), "+f"(c[1]), "+f"(c[2]), "+f"(c[3])
        : "r"(a0), "r"(a1), "r"(a2), "r"(a3), "r"(b0), "r"(b1));
}
__device__ __forceinline__ void ldm4(uint32_t& r0, uint32_t& r1, uint32_t& r2,
                                     uint32_t& r3, uint32_t addr) {
    asm volatile("ldmatrix.sync.aligned.m8n8.x4.shared.b16 {%0,%1,%2,%3}, [%4];"
        : "=r"(r0), "=r"(r1), "=r"(r2), "=r"(r3) : "r"(addr));
}

#define TSTRIDE 144                 // bytes per smem tile row (64 bf16 + 8 pad)
#define TILE_BYTES (128*TSTRIDE)    // 18432
#define HG_SMEM (6*TILE_BYTES)      // 110592: A x3 stages, B x3 stages

// ================= bf16 HMMA GEMM (K-chunk 64, 3-stage cp.async, ldmatrix) =========
// C[M,512] = Acat[M,Ktot] @ W[Ktot,512] + bias, then optional ⊙ scale[row/196, col]
// Acat[m,k] = (k<K1) ? A1[m,k] : A2[m,k-K1]   (A2 row stride 512, bf16)
// Bt = W^T bf16, [512][Ktot] row-major.
// grid = (N/128, M/128): x fastest => adjacent CTAs share the A tile (L2 reuse).
__global__ void __launch_bounds__(256, 2) hgemm_kernel(
    const __nv_bfloat16* __restrict__ A1,
    const __nv_bfloat16* __restrict__ A2,
    const __nv_bfloat16* __restrict__ Bt,
    const float* __restrict__ bias,
    const float* __restrict__ scale,
    void* __restrict__ Cout, int c_is_bf16,
    int K1, int Ktot)
{
    extern __shared__ char sm[];
    const uint32_t sa_base = smem_u32(sm);
    const uint32_t sb_base = sa_base + 3 * TILE_BYTES;

    const int tid  = threadIdx.x;
    const int m0   = blockIdx.y * 128;
    const int n0   = blockIdx.x * 128;
    const int warp = tid >> 5;
    const int lane = tid & 31;
    const int wm = warp >> 2;        // 0..1 (64 rows)
    const int wn = warp & 3;         // 0..3 (32 cols)
    const int g  = lane >> 2;
    const int t  = lane & 3;

    float acc[4][4][4];
    #pragma unroll
    for (int i = 0; i < 4; i++)
        #pragma unroll
        for (int j = 0; j < 4; j++)
            #pragma unroll
            for (int k = 0; k < 4; k++) acc[i][j][k] = 0.f;

    const int nch = Ktot >> 6;       // 64-wide K chunks

    auto load_tile = [&](int c) {
        const int kt = c << 6;
        const int s = c % 3;
        uint32_t ab = sa_base + s * TILE_BYTES;
        uint32_t bb = sb_base + s * TILE_BYTES;
        #pragma unroll
        for (int i = 0; i < 4; i++) {
            int chunk = tid + (i << 8);       // 0..1023
            int row = chunk >> 3, cc = chunk & 7;
            int kg = kt + (cc << 3);
            const __nv_bfloat16* sa = (kg < K1)
                ? (A1 + (size_t)(m0 + row) * K1 + kg)
                : (A2 + (size_t)(m0 + row) * Dz + (kg - K1));
            cp16(ab + row * TSTRIDE + cc * 16, sa);
            cp16(bb + row * TSTRIDE + cc * 16,
                 Bt + (size_t)(n0 + row) * Ktot + kt + (cc << 3));
        }
        asm volatile("cp.async.commit_group;" ::: "memory");
    };

    load_tile(0);
    load_tile(1);
    for (int c = 0; c < nch; c++) {
        if (c + 1 < nch) asm volatile("cp.async.wait_group 1;" ::: "memory");
        else             asm volatile("cp.async.wait_group 0;" ::: "memory");
        __syncthreads();
        if (c + 2 < nch) load_tile(c + 2);

        const int s = c % 3;
        const uint32_t ab = sa_base + s * TILE_BYTES;
        const uint32_t bb = sb_base + s * TILE_BYTES;
        #pragma unroll
        for (int ks = 0; ks < 4; ks++) {
            uint32_t bfr[4][2];
            #pragma unroll
            for (int j = 0; j < 2; j++) {
                uint32_t addr = bb + (uint32_t)((wn * 32 + j * 16 + ((lane >> 4) & 1) * 8
                                + (lane & 7)) * TSTRIDE + ks * 32 + ((lane >> 3) & 1) * 16);
                ldm4(bfr[2*j][0], bfr[2*j][1], bfr[2*j+1][0], bfr[2*j+1][1], addr);
            }
            #pragma unroll
            for (int am = 0; am < 4; am++) {
                uint32_t addr = ab + (uint32_t)((wm * 64 + am * 16 + (lane & 15)) * TSTRIDE
                                + ks * 32 + ((lane >> 4) & 1) * 16);
                uint32_t a0, a1, a2, a3;
                ldm4(a0, a1, a2, a3, addr);
                #pragma unroll
                for (int an = 0; an < 4; an++)
                    mma_bf16(acc[am][an], a0, a1, a2, a3, bfr[an][0], bfr[an][1]);
            }
        }
    }

    // ---- epilogue: c0:(g,2t) c1:(g,2t+1) c2:(g+8,2t) c3:(g+8,2t+1) ----
    #pragma unroll
    for (int am = 0; am < 4; am++) {
        int r0 = m0 + wm * 64 + am * 16 + g;
        int r1 = r0 + 8;
        #pragma unroll
        for (int an = 0; an < 4; an++) {
            int col = n0 + wn * 32 + an * 8 + t * 2;
            float b0 = bias[col], b1 = bias[col + 1];
            float v00 = acc[am][an][0] + b0, v01 = acc[am][an][1] + b1;
            float v10 = acc[am][an][2] + b0, v11 = acc[am][an][3] + b1;
            if (scale) {
                const float* s0 = scale + (size_t)(r0 / HWz) * Dz + col;
                const float* s1 = scale + (size_t)(r1 / HWz) * Dz + col;
                v00 *= s0[0]; v01 *= s0[1];
                v10 *= s1[0]; v11 *= s1[1];
            }
            if (c_is_bf16) {
                union { __nv_bfloat162 h; uint32_t u; } p0, p1;
                p0.h = __floats2bfloat162_rn(v00, v01);
                p1.h = __floats2bfloat162_rn(v10, v11);
                *(uint32_t*)((__nv_bfloat16*)Cout + (size_t)r0 * Dz + col) = p0.u;
                *(uint32_t*)((__nv_bfloat16*)Cout + (size_t)r1 * Dz + col) = p1.u;
            } else {
                *(float2*)((float*)Cout + (size_t)r0 * Dz + col) = make_float2(v00, v01);
                *(float2*)((float*)Cout + (size_t)r1 * Dz + col) = make_float2(v10, v11);
            }
        }
    }
}

// ---------------- fp32 -> bf16 bulk convert ----------------
__global__ void __launch_bounds__(256) f2bf_kernel(const float* __restrict__ in,
                                                   __nv_bfloat16* __restrict__ out)
{
    size_t i = ((size_t)blockIdx.x * 256 + threadIdx.x) * 4;
    float4 v = *(const float4*)(in + i);
    union { __nv_bfloat162 h; uint32_t u; } p0, p1;
    p0.h = __floats2bfloat162_rn(v.x, v.y);
    p1.h = __floats2bfloat162_rn(v.z, v.w);
    *(uint2*)(out + i) = make_uint2(p0.u, p1.u);
}

// ---------------- weight transpose: Wt[n][k] = (bf16) W[k][n] ----------------
__global__ void __launch_bounds__(256) transpose_w_kernel(
    const float* __restrict__ W, __nv_bfloat16* __restrict__ Wt, int K, int N)
{
    __shared__ float t[32][33];
    int k0 = blockIdx.x * 32, n0 = blockIdx.y * 32;
    int x = threadIdx.x & 31, y = threadIdx.x >> 5;
    #pragma unroll
    for (int j = 0; j < 32; j += 8)
        t[y + j][x] = W[(size_t)(k0 + y + j) * N + n0 + x];
    __syncthreads();
    #pragma unroll
    for (int j = 0; j < 32; j += 8)
        Wt[(size_t)(n0 + y + j) * K + k0 + x] = __float2bfloat16(t[x][y + j]);
}

// ---------------- fp32 SGEMM with concat-A and stacked-B support ----------------
// C[M,N] = concat(A1,A2)[M,Ktot] @ stack(B1,B2)[Ktot,N] + bias (+bias2)
__global__ void __launch_bounds__(256) sgemm_kernel(
    const float* __restrict__ A1, const float* __restrict__ A2,
    const float* __restrict__ B1, const float* __restrict__ B2,
    const float* __restrict__ bias, const float* __restrict__ bias2,
    float* __restrict__ C,
    int M, int N, int K1, int KB1, int Ktot)
{
    __shared__ float As[8][128];
    __shared__ float Bs[8][128];
    const int tid = threadIdx.x;
    const int m0 = blockIdx.y * 128;
    const int n0 = blockIdx.x * 128;
    const int tx = tid & 15;
    const int ty = tid >> 4;
    const int aRow = tid >> 1;
    const int aCol = (tid & 1) << 2;
    const int bRow = tid >> 5;
    const int bCol = (tid & 31) << 2;

    float acc[8][8];
    #pragma unroll
    for (int i = 0; i < 8; i++)
        #pragma unroll
        for (int j = 0; j < 8; j++) acc[i][j] = 0.f;

    for (int kt = 0; kt < Ktot; kt += 8) {
        int kg = kt + aCol;
        const float* ap = (kg < K1)
            ? (A1 + (size_t)(m0 + aRow) * K1 + kg)
            : (A2 + (size_t)(m0 + aRow) * Dz + (kg - K1));
        float4 a = *(const float4*)ap;
        As[aCol + 0][aRow] = a.x;
        As[aCol + 1][aRow] = a.y;
        As[aCol + 2][aRow] = a.z;
        As[aCol + 3][aRow] = a.w;
        int kr = kt + bRow;
        const float* bp = (kr < KB1)
            ? (B1 + (size_t)kr * N + n0 + bCol)
            : (B2 + (size_t)(kr - KB1) * N + n0 + bCol);
        *(float4*)&Bs[bRow][bCol] = *(const float4*)bp;
        __syncthreads();
        #pragma unroll
        for (int k = 0; k < 8; k++) {
            float ar[8], br[8];
            #pragma unroll
            for (int i = 0; i < 8; i++) ar[i] = As[k][ty * 8 + i];
            #pragma unroll
            for (int j = 0; j < 8; j++) br[j] = Bs[k][tx * 8 + j];
            #pragma unroll
            for (int i = 0; i < 8; i++)
                #pragma unroll
                for (int j = 0; j < 8; j++)
                    acc[i][j] = fmaf(ar[i], br[j], acc[i][j]);
        }
        __syncthreads();
    }
    #pragma unroll
    for (int i = 0; i < 8; i++) {
        int row = m0 + ty * 8 + i;
        float* crow = C + (size_t)row * N + n0 + tx * 8;
        #pragma unroll
        for (int j = 0; j < 8; j++) {
            float v = acc[i][j] + bias[n0 + tx * 8 + j];
            if (bias2) v += bias2[n0 + tx * 8 + j];
            crow[j] = v;
        }
    }
}

// ---------------- cai[b,s] = sum_d cqi[b,d]*cws[b,s,d]*W_cai[d] ----------------
__global__ void __launch_bounds__(256) cai_kernel(const float* __restrict__ cws,
                                                  const float* __restrict__ Wcai)
{
    int warp = (blockIdx.x * blockDim.x + threadIdx.x) >> 5;
    int lane = threadIdx.x & 31;
    if (warp >= Bz * Sz) return;
    int b = warp / Sz;
    const float* cq = g_cqi + b * Dz;
    const float* cw = cws + (size_t)warp * Dz;
    float sum = 0.f;
    #pragma unroll 4
    for (int d = lane; d < Dz; d += 32)
        sum += cq[d] * cw[d] * Wcai[d];
    #pragma unroll
    for (int o = 16; o; o >>= 1) sum += __shfl_xor_sync(0xffffffffu, sum, o);
    if (lane == 0) g_cai[warp] = sum;
}

// ---------------- softmax over S + ci reduction ----------------
__global__ void __launch_bounds__(128) ci_kernel(const float* __restrict__ cws)
{
    int b = blockIdx.x, tid = threadIdx.x;
    __shared__ float wsm[Sz];
    __shared__ float red[4];
    float x = g_cai[b * Sz + tid];
    float m = x;
    #pragma unroll
    for (int o = 16; o; o >>= 1) m = fmaxf(m, __shfl_xor_sync(0xffffffffu, m, o));
    if ((tid & 31) == 0) red[tid >> 5] = m;
    __syncthreads();
    float bm = fmaxf(fmaxf(red[0], red[1]), fmaxf(red[2], red[3]));
    __syncthreads();
    float e = expf(x - bm);
    float s = e;
    #pragma unroll
    for (int o = 16; o; o >>= 1) s += __shfl_xor_sync(0xffffffffu, s, o);
    if ((tid & 31) == 0) red[tid >> 5] = s;
    __syncthreads();
    float bs = red[0] + red[1] + red[2] + red[3];
    wsm[tid] = e / bs;
    __syncthreads();
    for (int d = tid; d < Dz; d += 128) {
        float acc = 0.f;
        #pragma unroll 8
        for (int s2 = 0; s2 < Sz; s2++)
            acc += wsm[s2] * cws[((size_t)b * Sz + s2) * Dz + d];
        g_ci[b * Dz + d] = acc;
    }
}

// ---------------- double softmax + ri, smem-staged (one global pass) ----------------
#define RS_SMEM (HWz*128*4)   // 196*128 fp32 = 100352 B
__global__ void __launch_bounds__(128) rsoft_kernel(const float* __restrict__ rai,
                                                    const float* __restrict__ Kt)
{
    extern __shared__ float sd[];   // [196][128]
    const int b = blockIdx.x;
    const int d0 = blockIdx.y * 128;
    const int tid = threadIdx.x;
    const float* src = rai + (size_t)b * HWz * Dz + d0;

    for (int i = tid; i < HWz * 32; i += 128) {
        int pos = i >> 5, c4 = (i & 31) << 2;
        *(float4*)(sd + pos * 128 + c4) = *(const float4*)(src + (size_t)pos * Dz + c4);
    }
    __syncthreads();

    for (int w = 0; w < Wz; w++) {
        float v[Hz];
        float mx = -1e30f;
        #pragma unroll
        for (int h = 0; h < Hz; h++) { v[h] = sd[(h * Wz + w) * 128 + tid]; mx = fmaxf(mx, v[h]); }
        float s = 0.f;
        #pragma unroll
        for (int h = 0; h < Hz; h++) { v[h] = expf(v[h] - mx); s += v[h]; }
        float inv = 1.f / s;
        #pragma unroll
        for (int h = 0; h < Hz; h++) sd[(h * Wz + w) * 128 + tid] = v[h] * inv;
    }
    __syncthreads();

    const float* kp = Kt + (size_t)b * HWz * Dz + d0 + tid;
    float acc = 0.f;
    for (int h = 0; h < Hz; h++) {
        float v[Wz];
        float mx = -1e30f;
        #pragma unroll
        for (int w = 0; w < Wz; w++) { v[w] = sd[(h * Wz + w) * 128 + tid]; mx = fmaxf(mx, v[w]); }
        float s = 0.f;
        #pragma unroll
        for (int w = 0; w < Wz; w++) { v[w] = expf(v[w] - mx); s += v[w]; }
        float inv = 1.f / s;
        #pragma unroll
        for (int w = 0; w < Wz; w++) acc += v[w] * inv * kp[(size_t)(h * Wz + w) * Dz];
    }
    g_ri[b * Dz + d0 + tid] = acc;
}

// ---------------- write attention ----------------
__global__ void __launch_bounds__(512) sa_kernel(const float* __restrict__ C_past,
                                                 const float* __restrict__ M_past,
                                                 const float* __restrict__ Wwcc)
{
    int b = blockIdx.x, tid = threadIdx.x;
    int lane = tid & 31, warp = tid >> 5;
    __shared__ float z[16];
    __shared__ float wsm[Tz];
    if (warp < Tz) {
        const float* cp = C_past + ((size_t)b * Tz + warp) * Dz;
        const float* cb = g_ci + b * Dz;
        float sum = 0.f;
        #pragma unroll 4
        for (int d = lane; d < Dz; d += 32) sum += cb[d] * cp[d] * Wwcc[d];
        #pragma unroll
        for (int o = 16; o; o >>= 1) sum += __shfl_xor_sync(0xffffffffu, sum, o);
        if (lane == 0) z[warp] = sum;
    }
    __syncthreads();
    if (tid == 0) {
        float mx = -1e30f;
        for (int t = 0; t < Tz; t++) mx = fmaxf(mx, z[t]);
        float s = 0.f;
        for (int t = 0; t < Tz; t++) { float e = expf(z[t] - mx); wsm[t] = e; s += e; }
        float inv = 1.f / s;
        for (int t = 0; t < Tz; t++) wsm[t] *= inv;
    }
    __syncthreads();
    float acc = 0.f;
    #pragma unroll
    for (int t = 0; t < Tz; t++)
        acc += wsm[t] * M_past[((size_t)b * Tz + t) * Dz + tid];
    g_mi_sa[b * Dz + tid] = acc;
}

// ---------------- gate + final ----------------
__global__ void __launch_bounds__(512) final_kernel(const float* __restrict__ mi_1,
                                                    const float* __restrict__ Wwci,
                                                    const float* __restrict__ bwci,
                                                    float* __restrict__ out)
{
    int b = blockIdx.x, tid = threadIdx.x;
    __shared__ float red[16];
    __shared__ float gsh;
    float civ = g_ci[b * Dz + tid];
    float sum = civ * Wwci[tid];
    #pragma unroll
    for (int o = 16; o; o >>= 1) sum += __shfl_xor_sync(0xffffffffu, sum, o);
    if ((tid & 31) == 0) red[tid >> 5] = sum;
    __syncthreads();
    if (tid < 32) {
        float v = (tid < 16) ? red[tid] : 0.f;
        #pragma unroll
        for (int o = 8; o; o >>= 1) v += __shfl_xor_sync(0xffffffffu, v, o);
        if (tid == 0) gsh = 1.f / (1.f + expf(-(v + bwci[0])));
    }
    __syncthreads();
    float g = gsh;
    float mi = g * mi_1[b * Dz + tid] + (1.f - g) * g_mi_prime[b * Dz + tid];
    out[b * Dz + tid] = civ;
    out[(size_t)Bz * Dz + b * Dz + tid] = mi;
}

// ---------------- launch ----------------
extern "C" void kernel_launch(void* const* d_in, const int* in_sizes, int n_in,
                              void* d_out, int out_size)
{
    const float* ci_1   = (const float*)d_in[0];
    const float* mi_1   = (const float*)d_in[1];
    const float* q      = (const float*)d_in[2];
    const float* cws    = (const float*)d_in[3];
    const float* Kt     = (const float*)d_in[4];
    const float* C_past = (const float*)d_in[5];
    const float* M_past = (const float*)d_in[6];
    const float* W_cq   = (const float*)d_in[7];
    const float* b_cq   = (const float*)d_in[8];
    const float* W_cqi  = (const float*)d_in[9];
    const float* b_cqi  = (const float*)d_in[10];
    const float* W_cai  = (const float*)d_in[11];
    const float* W_rm   = (const float*)d_in[13];
    const float* b_rm   = (const float*)d_in[14];
    const float* W_rk   = (const float*)d_in[15];
    const float* b_rk   = (const float*)d_in[16];
    const float* W_rik  = (const float*)d_in[17];
    const float* b_rik  = (const float*)d_in[18];
    const float* W_rci  = (const float*)d_in[19];
    const float* b_rci  = (const float*)d_in[20];
    const float* W_wrm  = (const float*)d_in[21];
    const float* b_wrm  = (const float*)d_in[22];
    const float* W_wcc  = (const float*)d_in[23];
    const float* W_wsa  = (const float*)d_in[25];
    const float* b_wsa  = (const float*)d_in[26];
    const float* W_winfo= (const float*)d_in[27];
    const float* b_winfo= (const float*)d_in[28];
    const float* W_wci  = (const float*)d_in[29];
    const float* b_wci  = (const float*)d_in[30];
    float* out = (float*)d_out;

    float *qi, *cqi, *ci, *rm, *rai, *ri, *mi_info, *mi_sa, *mi_prime;
    __nv_bfloat16 *K_bf, *rk_bf, *ip_bf, *Wt_rk, *Wt_rik, *Wt_rci;
    cudaGetSymbolAddress((void**)&qi, g_qi);
    cudaGetSymbolAddress((void**)&cqi, g_cqi);
    cudaGetSymbolAddress((void**)&ci, g_ci);
    cudaGetSymbolAddress((void**)&rm, g_rm);
    cudaGetSymbolAddress((void**)&rai, g_rai);
    cudaGetSymbolAddress((void**)&ri, g_ri);
    cudaGetSymbolAddress((void**)&mi_info, g_mi_info);
    cudaGetSymbolAddress((void**)&mi_sa, g_mi_sa);
    cudaGetSymbolAddress((void**)&mi_prime, g_mi_prime);
    cudaGetSymbolAddress((void**)&K_bf, g_K_bf);
    cudaGetSymbolAddress((void**)&rk_bf, g_rk_bf);
    cudaGetSymbolAddress((void**)&ip_bf, g_ip_bf);
    cudaGetSymbolAddress((void**)&Wt_rk, g_Wt_rk);
    cudaGetSymbolAddress((void**)&Wt_rik, g_Wt_rik);
    cudaGetSymbolAddress((void**)&Wt_rci, g_Wt_rci);

    cudaFuncSetAttribute(hgemm_kernel,
                         cudaFuncAttributeMaxDynamicSharedMemorySize, HG_SMEM);
    cudaFuncSetAttribute(rsoft_kernel,
                         cudaFuncAttributeMaxDynamicSharedMemorySize, RS_SMEM);

    dim3 gs(Dz / 128, Bz / 128);     // small GEMMs: (4, 2)
    dim3 gh(Dz / 128, Mbig / 128);   // big GEMMs: (4, 392) — N fastest for A L2 reuse

    // ---- precompute: bf16 conversions ----
    f2bf_kernel<<<(Mbig * Dz) / 1024, 256>>>(Kt, K_bf);
    transpose_w_kernel<<<dim3(Dz/32, Dz/32), 256>>>(W_rk, Wt_rk, Dz, Dz);
    transpose_w_kernel<<<dim3(2*Dz/32, Dz/32), 256>>>(W_rik, Wt_rik, 2*Dz, Dz);
    transpose_w_kernel<<<dim3(Dz/32, Dz/32), 256>>>(W_rci, Wt_rci, Dz, Dz);

    // ---- control (fp32) ----
    sgemm_kernel<<<gs, 256>>>(q, nullptr, W_cq, nullptr, b_cq, nullptr, qi,
                              Bz, Dz, Dz, 2*Dz, Dz);
    sgemm_kernel<<<gs, 256>>>(ci_1, qi, W_cqi, nullptr, b_cqi, nullptr, cqi,
                              Bz, Dz, Dz, 2*Dz, 2*Dz);
    cai_kernel<<<(Bz * Sz) / 8, 256>>>(cws, W_cai);
    ci_kernel<<<Bz, 128>>>(cws);

    // ---- read (bf16 HMMA big GEMMs, scalings folded into epilogues) ----
    sgemm_kernel<<<gs, 256>>>(mi_1, nullptr, W_rm, nullptr, b_rm, nullptr, rm,
                              Bz, Dz, Dz, 2*Dz, Dz);
    // rk_bf = rm ⊙ (K @ W_rk + b_rk)
    hgemm_kernel<<<gh, 256, HG_SMEM>>>(K_bf, nullptr, Wt_rk, b_rk, rm, rk_bf, 1, Dz, Dz);
    // ip_bf = ci ⊙ (concat(rk_bf, K) @ W_rik + b_rik)
    hgemm_kernel<<<gh, 256, HG_SMEM>>>(rk_bf, K_bf, Wt_rik, b_rik, ci, ip_bf, 1, Dz, 2*Dz);
    // rai = ip_bf @ W_rci + b_rci  (fp32 out)
    hgemm_kernel<<<gh, 256, HG_SMEM>>>(ip_bf, nullptr, Wt_rci, b_rci, nullptr, rai, 0, Dz, Dz);
    rsoft_kernel<<<dim3(Bz, Dz/128), 128, RS_SMEM>>>(rai, Kt);

    // ---- write (fp32) ----
    sgemm_kernel<<<gs, 256>>>(ri, mi_1, W_wrm, nullptr, b_wrm, nullptr, mi_info,
                              Bz, Dz, Dz, 2*Dz, 2*Dz);
    sa_kernel<<<Bz, 512>>>(C_past, M_past, W_wcc);
    sgemm_kernel<<<gs, 256>>>(mi_sa, mi_info, W_wsa, W_winfo, b_wsa, b_winfo, mi_prime,
                              Bz, Dz, Dz, Dz, 2*Dz);
    final_kernel<<<Bz, 512>>>(mi_1, W_wci, b_wci, out);
}